// round 10
// baseline (speedup 1.0000x reference)
#include <cuda_runtime.h>
#include <cuda_bf16.h>
#include <cstdint>
#include <math.h>

#define BDIM 8
#define NDIM 1024
#define DMODEL 512
#define HH 8
#define DKH 64
#define ST 128
#define MROWS (BDIM * NDIM)
#define WSZ (DMODEL * DMODEL)

// ---------------- scratch (device globals) ----------------
__device__ float g_q[MROWS * DMODEL];
__device__ float g_k[MROWS * DMODEL];
__device__ float g_v[MROWS * DMODEL];
__device__ float g_y[MROWS * DMODEL];
__device__ __nv_bfloat16 g_ahi[MROWS * DMODEL];
__device__ __nv_bfloat16 g_alo[MROWS * DMODEL];
__device__ __nv_bfloat16 g_chi[MROWS * DMODEL];
__device__ __nv_bfloat16 g_clo[MROWS * DMODEL];
__device__ __nv_bfloat16 g_whi[4 * WSZ];
__device__ __nv_bfloat16 g_wlo[4 * WSZ];

__device__ __forceinline__ uint32_t smem_to_u32(const void* smem_ptr) {
    uint32_t addr;
    asm("{ .reg .u64 tmp; cvta.to.shared.u64 tmp, %1; cvt.u32.u64 %0, tmp; }"
        : "=r"(addr) : "l"(smem_ptr));
    return addr;
}

#define LDSM_X4(r0, r1, r2, r3, addr)                                          \
    asm volatile("ldmatrix.sync.aligned.m8n8.x4.shared.b16 {%0,%1,%2,%3}, [%4];" \
                 : "=r"(r0), "=r"(r1), "=r"(r2), "=r"(r3) : "r"(addr))

// ---------------------------------------------------------------------------
// split fp32 -> bf16 hi + bf16 lo (residual)
// ---------------------------------------------------------------------------
__global__ __launch_bounds__(256) void split_kernel(
    const float* __restrict__ x, __nv_bfloat16* __restrict__ hi,
    __nv_bfloat16* __restrict__ lo, int n4)
{
    int i = blockIdx.x * 256 + threadIdx.x;
    if (i >= n4) return;
    float4 v = ((const float4*)x)[i];
    union { __nv_bfloat16 b[4]; uint2 u; } H, L;
    H.b[0] = __float2bfloat16(v.x);
    H.b[1] = __float2bfloat16(v.y);
    H.b[2] = __float2bfloat16(v.z);
    H.b[3] = __float2bfloat16(v.w);
    L.b[0] = __float2bfloat16(v.x - __bfloat162float(H.b[0]));
    L.b[1] = __float2bfloat16(v.y - __bfloat162float(H.b[1]));
    L.b[2] = __float2bfloat16(v.z - __bfloat162float(H.b[2]));
    L.b[3] = __float2bfloat16(v.w - __bfloat162float(H.b[3]));
    ((uint2*)hi)[i] = H.u;
    ((uint2*)lo)[i] = L.u;
}

// fused 4-weight split: blockIdx.y selects which weight matrix
__global__ __launch_bounds__(256) void split4_kernel(
    const float* __restrict__ w0, const float* __restrict__ w1,
    const float* __restrict__ w2, const float* __restrict__ w3,
    __nv_bfloat16* __restrict__ hi, __nv_bfloat16* __restrict__ lo)
{
    const int z = blockIdx.y;
    const float* src = (z == 0) ? w0 : (z == 1) ? w1 : (z == 2) ? w2 : w3;
    int i = blockIdx.x * 256 + threadIdx.x;
    float4 v = ((const float4*)src)[i];
    union { __nv_bfloat16 b[4]; uint2 u; } H, L;
    H.b[0] = __float2bfloat16(v.x);
    H.b[1] = __float2bfloat16(v.y);
    H.b[2] = __float2bfloat16(v.z);
    H.b[3] = __float2bfloat16(v.w);
    L.b[0] = __float2bfloat16(v.x - __bfloat162float(H.b[0]));
    L.b[1] = __float2bfloat16(v.y - __bfloat162float(H.b[1]));
    L.b[2] = __float2bfloat16(v.z - __bfloat162float(H.b[2]));
    L.b[3] = __float2bfloat16(v.w - __bfloat162float(H.b[3]));
    ((uint2*)(hi + (size_t)z * WSZ))[i] = H.u;
    ((uint2*)(lo + (size_t)z * WSZ))[i] = L.u;
}

// ---------------------------------------------------------------------------
// HMMA split-bf16 GEMM, 8 warps (each 64x32), ldmatrix + 4-stage cp.async.
// C[m][n] = sum_k A[m][k]*W[n][k] (+bias)(+resid), via
// Ahi*Bhi + Ahi*Blo + Alo*Bhi with fp32 accum (mma.sync.m16n8k16).
// CTA 128x128, 48 chunks of K=32 (3 passes x 16). blockIdx.z: QKV fusion.
// ---------------------------------------------------------------------------
#define SASTR 40
#define HALF_STAGE 10240            // 128 * 40 * 2 bytes
#define STAGE_BYTES 20480
#define GEMM_SMEM (4 * STAGE_BYTES) // 81920

__global__ __launch_bounds__(256) void gemm_tc(
    const __nv_bfloat16* __restrict__ Ahi, const __nv_bfloat16* __restrict__ Alo,
    const __nv_bfloat16* __restrict__ BhiBase, const __nv_bfloat16* __restrict__ BloBase,
    const float* __restrict__ bias, const float* __restrict__ resid,
    float* __restrict__ C0, float* __restrict__ C1, float* __restrict__ C2)
{
    extern __shared__ char smem[];
    const uint32_t smem_base = smem_to_u32(smem);
    const int tid = threadIdx.x;
    const int lane = tid & 31, warp = tid >> 5;
    const int z = blockIdx.z;
    const __nv_bfloat16* Bhi = BhiBase + (size_t)z * WSZ;
    const __nv_bfloat16* Blo = BloBase + (size_t)z * WSZ;
    float* C = (z == 0) ? C0 : (z == 1) ? C1 : C2;
    const int n0 = blockIdx.x * 128, m0 = blockIdx.y * 128;
    const int wm0 = (warp >> 2) * 64, wn0 = (warp & 3) * 32;

    // ldmatrix lane address components
    const int a_row = wm0 + (lane & 15);
    const int a_coff = (lane >> 4) * 8;
    const int b_row = wn0 + (lane & 7) + ((lane >> 4) << 3);
    const int b_coff = ((lane >> 3) & 1) * 8;

    float acc[4][4][4];
#pragma unroll
    for (int mt = 0; mt < 4; mt++)
#pragma unroll
        for (int nt = 0; nt < 4; nt++)
#pragma unroll
            for (int c = 0; c < 4; c++) acc[mt][nt][c] = 0.f;

#define ISSUE_LOAD(sidx, Ap, Bp, kk0) do {                                     \
    int _row = tid >> 1, _hf = tid & 1;                                        \
    uint32_t _sa = smem_base + (sidx) * STAGE_BYTES + _row * 80 + _hf * 32;    \
    uint32_t _sb = _sa + HALF_STAGE;                                           \
    const __nv_bfloat16* _ga = (Ap) + (size_t)(m0 + _row) * DMODEL + (kk0) + _hf * 16; \
    const __nv_bfloat16* _gb = (Bp) + (size_t)(n0 + _row) * DMODEL + (kk0) + _hf * 16; \
    asm volatile("cp.async.cg.shared.global [%0], [%1], 16;"                   \
                 :: "r"(_sa), "l"(_ga) : "memory");                            \
    asm volatile("cp.async.cg.shared.global [%0], [%1], 16;"                   \
                 :: "r"(_sa + 16), "l"(_ga + 8) : "memory");                   \
    asm volatile("cp.async.cg.shared.global [%0], [%1], 16;"                   \
                 :: "r"(_sb), "l"(_gb) : "memory");                            \
    asm volatile("cp.async.cg.shared.global [%0], [%1], 16;"                   \
                 :: "r"(_sb + 16), "l"(_gb + 8) : "memory");                   \
} while (0)

#define CHUNK_SRC(idx, Ap, Bp, K0) \
    const int _p = (idx) >> 4; const int K0 = ((idx) & 15) * 32;               \
    const __nv_bfloat16* Ap = (_p == 2) ? Alo : Ahi;                           \
    const __nv_bfloat16* Bp = (_p == 1) ? Blo : Bhi;

    // prologue: 3 stages in flight
#pragma unroll
    for (int s = 0; s < 3; s++) {
        CHUNK_SRC(s, Ap, Bp, k0);
        ISSUE_LOAD(s, Ap, Bp, k0);
        asm volatile("cp.async.commit_group;" ::: "memory");
    }

    for (int i = 0; i < 48; i++) {
        asm volatile("cp.async.wait_group 2;" ::: "memory");
        __syncthreads();

        const uint32_t As_b = smem_base + (i & 3) * STAGE_BYTES;
        const uint32_t Bs_b = As_b + HALF_STAGE;

#pragma unroll
        for (int ks = 0; ks < 2; ks++) {
            uint32_t af[4][4];
            uint32_t bfr[4][2];
#pragma unroll
            for (int mt = 0; mt < 4; mt++) {
                uint32_t ad = As_b + (uint32_t)(((a_row + mt * 16) * SASTR) + ks * 16 + a_coff) * 2;
                LDSM_X4(af[mt][0], af[mt][1], af[mt][2], af[mt][3], ad);
            }
#pragma unroll
            for (int np = 0; np < 2; np++) {
                uint32_t bd = Bs_b + (uint32_t)(((b_row + np * 16) * SASTR) + ks * 16 + b_coff) * 2;
                LDSM_X4(bfr[np * 2][0], bfr[np * 2][1], bfr[np * 2 + 1][0], bfr[np * 2 + 1][1], bd);
            }
#pragma unroll
            for (int mt = 0; mt < 4; mt++)
#pragma unroll
                for (int nt = 0; nt < 4; nt++) {
                    asm volatile(
                        "mma.sync.aligned.m16n8k16.row.col.f32.bf16.bf16.f32 "
                        "{%0,%1,%2,%3}, {%4,%5,%6,%7}, {%8,%9}, {%0,%1,%2,%3};"
                        : "+f"(acc[mt][nt][0]), "+f"(acc[mt][nt][1]),
                          "+f"(acc[mt][nt][2]), "+f"(acc[mt][nt][3])
                        : "r"(af[mt][0]), "r"(af[mt][1]), "r"(af[mt][2]), "r"(af[mt][3]),
                          "r"(bfr[nt][0]), "r"(bfr[nt][1]));
                }
        }

        const int nxt = i + 3;
        if (nxt < 48) {
            CHUNK_SRC(nxt, Ap, Bp, k0);
            ISSUE_LOAD((nxt & 3), Ap, Bp, k0);
        }
        asm volatile("cp.async.commit_group;" ::: "memory");
    }

    // epilogue
#pragma unroll
    for (int mt = 0; mt < 4; mt++) {
        const int r = m0 + wm0 + mt * 16 + (lane >> 2);
#pragma unroll
        for (int nt = 0; nt < 4; nt++) {
            const int cn = n0 + wn0 + nt * 8 + (lane & 3) * 2;
            float2 v0 = make_float2(acc[mt][nt][0], acc[mt][nt][1]);
            float2 v1 = make_float2(acc[mt][nt][2], acc[mt][nt][3]);
            if (bias) {
                float2 b2 = *(const float2*)(bias + cn);
                v0.x += b2.x; v0.y += b2.y;
                v1.x += b2.x; v1.y += b2.y;
            }
            if (resid) {
                float2 r0 = *(const float2*)(resid + (size_t)r * DMODEL + cn);
                float2 r1 = *(const float2*)(resid + (size_t)(r + 8) * DMODEL + cn);
                v0.x += r0.x; v0.y += r0.y;
                v1.x += r1.x; v1.y += r1.y;
            }
            *(float2*)(C + (size_t)r * DMODEL + cn) = v0;
            *(float2*)(C + (size_t)(r + 8) * DMODEL + cn) = v1;
        }
    }
}

// ---------------------------------------------------------------------------
// Star attention v3: no Vs smem (V via gmem/L2 in phase 3), S aliases Qs/Ks,
// self-dot precomputed, epilogue writes bf16 hi/lo split directly.
// smem 67.5KB -> 3 CTAs/SM.
// ---------------------------------------------------------------------------
#define QS_STR 132
#define S_STR  132
#define OFF_KS (DKH * QS_STR)            // 8448
#define OFF_SD (2 * DKH * QS_STR)        // 16896 (S aliases [0..16896))
#define OFF_ZR (OFF_SD + 128)
#define OFF_PS (OFF_ZR + 128)
#define ATTN_SMEM ((OFF_PS + 128) * 4)   // 69120 bytes

__global__ __launch_bounds__(256, 3) void attn_kernel(
    const float* __restrict__ q, const float* __restrict__ k,
    const float* __restrict__ v, const float* __restrict__ rpe,
    __nv_bfloat16* __restrict__ chi, __nv_bfloat16* __restrict__ clo)
{
    extern __shared__ float sm[];
    float* Qs = sm;
    float* Ks = sm + OFF_KS;
    float* S  = sm;                 // aliases Qs/Ks after phase 1
    float* sd = sm + OFF_SD;
    float* Zr = sm + OFF_ZR;
    float* Ps = sm + OFF_PS;

    const int tid = threadIdx.x;
    const int tx = tid & 15, ty = tid >> 4;
    const int qc = blockIdx.x, h = blockIdx.y, b = blockIdx.z;
    const int i0 = qc * 128;
    const bool has_self = (qc > 0);
    const int lane = tid & 31, wid = tid >> 5;

    const float* rpe_bh = rpe + ((size_t)(b * HH + h)) * NDIM * NDIM;

    // ---- self-dot precompute (pairs of threads per query) ----
    if (has_self) {
        const int i = tid >> 1;
        const int dh = (tid & 1) * 32;
        const float* qrow = q + ((size_t)(b * NDIM + i0 + i)) * DMODEL + h * DKH + dh;
        const float* krow = k + ((size_t)(b * NDIM + i0 + i)) * DMODEL + h * DKH + dh;
        float p = 0.f;
#pragma unroll
        for (int d = 0; d < 32; d += 4) {
            float4 q4 = *(const float4*)(qrow + d);
            float4 k4 = *(const float4*)(krow + d);
            p = fmaf(q4.x, k4.x, p);
            p = fmaf(q4.y, k4.y, p);
            p = fmaf(q4.z, k4.z, p);
            p = fmaf(q4.w, k4.w, p);
        }
        p += __shfl_xor_sync(0xffffffffu, p, 1);
        if (!(tid & 1))
            sd[i] = (p + rpe_bh[(size_t)(i0 + i) * NDIM + (i0 + i)]) * 0.125f;
    }

    // ---- load Q (transposed), K stations (transposed) ----
#pragma unroll
    for (int l = 0; l < 8; l++) {
        int idx = tid + l * 256;
        int row = idx >> 4, c = idx & 15;
        float4 va = *(const float4*)(q + ((size_t)(b * NDIM + i0 + row)) * DMODEL + h * DKH + c * 4);
        Qs[(c * 4 + 0) * QS_STR + row] = va.x;
        Qs[(c * 4 + 1) * QS_STR + row] = va.y;
        Qs[(c * 4 + 2) * QS_STR + row] = va.z;
        Qs[(c * 4 + 3) * QS_STR + row] = va.w;
        float4 vk = *(const float4*)(k + ((size_t)(b * NDIM + row)) * DMODEL + h * DKH + c * 4);
        Ks[(c * 4 + 0) * QS_STR + row] = vk.x;
        Ks[(c * 4 + 1) * QS_STR + row] = vk.y;
        Ks[(c * 4 + 2) * QS_STR + row] = vk.z;
        Ks[(c * 4 + 3) * QS_STR + row] = vk.w;
    }
    __syncthreads();

    // ---- Phase 1: S = Q.K^T in registers, write into aliased S ----
    {
        float acc[8][8];
#pragma unroll
        for (int i = 0; i < 8; i++)
#pragma unroll
            for (int j = 0; j < 8; j++) acc[i][j] = 0.f;

#pragma unroll 8
        for (int kk = 0; kk < DKH; kk++) {
            float a[8], bb[8];
            *(float4*)&a[0]  = *(float4*)&Qs[kk * QS_STR + ty * 4];
            *(float4*)&a[4]  = *(float4*)&Qs[kk * QS_STR + 64 + ty * 4];
            *(float4*)&bb[0] = *(float4*)&Ks[kk * QS_STR + tx * 4];
            *(float4*)&bb[4] = *(float4*)&Ks[kk * QS_STR + 64 + tx * 4];
#pragma unroll
            for (int i = 0; i < 8; i++)
#pragma unroll
                for (int j = 0; j < 8; j++)
                    acc[i][j] = fmaf(a[i], bb[j], acc[i][j]);
        }
        __syncthreads();   // Qs/Ks reads complete before S overwrite
#pragma unroll
        for (int i = 0; i < 8; i++) {
            int m = (i < 4) ? (ty * 4 + i) : (64 + ty * 4 + i - 4);
#pragma unroll
            for (int jh = 0; jh < 2; jh++) {
                int n = jh * 64 + tx * 4;
                float4 r4 = *(const float4*)(rpe_bh + (size_t)(i0 + m) * NDIM + n);
                float4 c;
                c.x = (acc[i][jh * 4 + 0] + r4.x) * 0.125f;
                c.y = (acc[i][jh * 4 + 1] + r4.y) * 0.125f;
                c.z = (acc[i][jh * 4 + 2] + r4.z) * 0.125f;
                c.w = (acc[i][jh * 4 + 3] + r4.w) * 0.125f;
                *(float4*)(S + m * S_STR + n) = c;
            }
        }
    }
    __syncthreads();

    // ---- Phase 2: row softmax ----
    for (int r16 = 0; r16 < 16; r16++) {
        int i = wid * 16 + r16;
        float4 x = *(float4*)(S + i * S_STR + lane * 4);
        float mx = fmaxf(fmaxf(x.x, x.y), fmaxf(x.z, x.w));
#pragma unroll
        for (int off = 16; off > 0; off >>= 1)
            mx = fmaxf(mx, __shfl_xor_sync(0xffffffffu, mx, off));

        float s_self = -3.0e38f;
        if (has_self) {
            s_self = sd[i];
            mx = fmaxf(mx, s_self);
        }

        float4 e;
        e.x = __expf(x.x - mx);
        e.y = __expf(x.y - mx);
        e.z = __expf(x.z - mx);
        e.w = __expf(x.w - mx);
        *(float4*)(S + i * S_STR + lane * 4) = e;
        float sum = e.x + e.y + e.z + e.w;
#pragma unroll
        for (int off = 16; off > 0; off >>= 1)
            sum += __shfl_xor_sync(0xffffffffu, sum, off);

        float pself = has_self ? __expf(s_self - mx) : 0.f;
        if (lane == 0) {
            Zr[i] = sum + pself;
            Ps[i] = pself;
        }
    }
    __syncthreads();

    // ---- Phase 3: ctx = P.V, V from gmem (L2-resident) ----
    {
        float acc[8][4];
#pragma unroll
        for (int i = 0; i < 8; i++)
#pragma unroll
            for (int j = 0; j < 4; j++) acc[i][j] = 0.f;

        const int ibase = ty * 8;
        const float* vptr = v + ((size_t)b * NDIM) * DMODEL + h * DKH + tx * 4;
#pragma unroll 4
        for (int j = 0; j < ST; j++) {
            float4 v4 = *(const float4*)(vptr + (size_t)j * DMODEL);
#pragma unroll
            for (int r = 0; r < 8; r++) {
                float p = S[(ibase + r) * S_STR + j];
                acc[r][0] = fmaf(p, v4.x, acc[r][0]);
                acc[r][1] = fmaf(p, v4.y, acc[r][1]);
                acc[r][2] = fmaf(p, v4.z, acc[r][2]);
                acc[r][3] = fmaf(p, v4.w, acc[r][3]);
            }
        }

#pragma unroll
        for (int r = 0; r < 8; r++) {
            int i = ibase + r;
            float invZ = 1.f / Zr[i];
            float4 o;
            o.x = acc[r][0]; o.y = acc[r][1]; o.z = acc[r][2]; o.w = acc[r][3];
            if (has_self) {
                float ps = Ps[i];
                float4 vs = *(const float4*)(v + ((size_t)(b * NDIM + i0 + i)) * DMODEL + h * DKH + tx * 4);
                o.x = fmaf(ps, vs.x, o.x);
                o.y = fmaf(ps, vs.y, o.y);
                o.z = fmaf(ps, vs.z, o.z);
                o.w = fmaf(ps, vs.w, o.w);
            }
            o.x *= invZ; o.y *= invZ; o.z *= invZ; o.w *= invZ;
            // direct bf16 hi/lo split store
            union { __nv_bfloat16 bb[4]; uint2 u; } H, L;
            H.bb[0] = __float2bfloat16(o.x);
            H.bb[1] = __float2bfloat16(o.y);
            H.bb[2] = __float2bfloat16(o.z);
            H.bb[3] = __float2bfloat16(o.w);
            L.bb[0] = __float2bfloat16(o.x - __bfloat162float(H.bb[0]));
            L.bb[1] = __float2bfloat16(o.y - __bfloat162float(H.bb[1]));
            L.bb[2] = __float2bfloat16(o.z - __bfloat162float(H.bb[2]));
            L.bb[3] = __float2bfloat16(o.w - __bfloat162float(H.bb[3]));
            size_t off = ((size_t)(b * NDIM + i0 + i)) * DMODEL + h * DKH + tx * 4;
            *(uint2*)(chi + off) = H.u;
            *(uint2*)(clo + off) = L.u;
        }
    }
}

// ---------------------------------------------------------------------------
// LayerNorm over rows of 512.
// ---------------------------------------------------------------------------
__global__ __launch_bounds__(128) void ln_kernel(
    const float* __restrict__ y, const float* __restrict__ g,
    const float* __restrict__ bta, float* __restrict__ out)
{
    __shared__ float sh1[4], sh2[4];
    const int row = blockIdx.x, t = threadIdx.x;
    const int lane = t & 31, wid = t >> 5;

    float4 vv = *(const float4*)(y + (size_t)row * DMODEL + t * 4);
    float s  = vv.x + vv.y + vv.z + vv.w;
    float s2 = vv.x * vv.x + vv.y * vv.y + vv.z * vv.z + vv.w * vv.w;
#pragma unroll
    for (int off = 16; off > 0; off >>= 1) {
        s  += __shfl_xor_sync(0xffffffffu, s, off);
        s2 += __shfl_xor_sync(0xffffffffu, s2, off);
    }
    if (lane == 0) { sh1[wid] = s; sh2[wid] = s2; }
    __syncthreads();
    float tot  = sh1[0] + sh1[1] + sh1[2] + sh1[3];
    float tot2 = sh2[0] + sh2[1] + sh2[2] + sh2[3];
    float mu  = tot * (1.f / 512.f);
    float var = tot2 * (1.f / 512.f) - mu * mu;
    float rs  = rsqrtf(var + 1e-6f);

    float4 gg = *(const float4*)(g + t * 4);
    float4 bb = *(const float4*)(bta + t * 4);
    float4 o;
    o.x = (vv.x - mu) * rs * gg.x + bb.x;
    o.y = (vv.y - mu) * rs * gg.y + bb.y;
    o.z = (vv.z - mu) * rs * gg.z + bb.z;
    o.w = (vv.w - mu) * rs * gg.w + bb.w;
    *(float4*)(out + (size_t)row * DMODEL + t * 4) = o;
}

// ---------------------------------------------------------------------------
extern "C" void kernel_launch(void* const* d_in, const int* in_sizes, int n_in,
                              void* d_out, int out_size)
{
    const float* hidden = (const float*)d_in[0];
    const float* rpe    = (const float*)d_in[1];
    const float* Wq     = (const float*)d_in[2];
    const float* Wk     = (const float*)d_in[3];
    const float* Wv     = (const float*)d_in[4];
    const float* fcw    = (const float*)d_in[5];
    const float* fcb    = (const float*)d_in[6];
    const float* lng    = (const float*)d_in[7];
    const float* lnb    = (const float*)d_in[8];
    float* out = (float*)d_out;

    float *qb, *kb, *vb, *yb;
    __nv_bfloat16 *ahi, *alo, *chi, *clo, *whi, *wlo;
    cudaGetSymbolAddress((void**)&qb, g_q);
    cudaGetSymbolAddress((void**)&kb, g_k);
    cudaGetSymbolAddress((void**)&vb, g_v);
    cudaGetSymbolAddress((void**)&yb, g_y);
    cudaGetSymbolAddress((void**)&ahi, g_ahi);
    cudaGetSymbolAddress((void**)&alo, g_alo);
    cudaGetSymbolAddress((void**)&chi, g_chi);
    cudaGetSymbolAddress((void**)&clo, g_clo);
    cudaGetSymbolAddress((void**)&whi, g_whi);
    cudaGetSymbolAddress((void**)&wlo, g_wlo);

    static int attr_set = 0;
    if (!attr_set) {
        cudaFuncSetAttribute(gemm_tc, cudaFuncAttributeMaxDynamicSharedMemorySize, GEMM_SMEM);
        cudaFuncSetAttribute(attn_kernel, cudaFuncAttributeMaxDynamicSharedMemorySize, ATTN_SMEM);
        attr_set = 1;
    }

    const int n4h = MROWS * DMODEL / 4;
    const int n4w = WSZ / 4;

    split_kernel<<<n4h / 256, 256>>>(hidden, ahi, alo, n4h);
    split4_kernel<<<dim3(n4w / 256, 4), 256>>>(Wq, Wk, Wv, fcw, whi, wlo);

    // fused QKV
    gemm_tc<<<dim3(DMODEL / 128, MROWS / 128, 3), 256, GEMM_SMEM>>>(
        ahi, alo, whi, wlo, nullptr, nullptr, qb, kb, vb);

    attn_kernel<<<dim3(NDIM / 128, HH, BDIM), 256, ATTN_SMEM>>>(qb, kb, vb, rpe, chi, clo);

    gemm_tc<<<dim3(DMODEL / 128, MROWS / 128, 1), 256, GEMM_SMEM>>>(
        chi, clo, whi + 3 * WSZ, wlo + 3 * WSZ, fcb, hidden, yb, yb, yb);

    ln_kernel<<<MROWS, 128>>>(yb, lng, lnb, out);
}

// round 12
// speedup vs baseline: 1.2390x; 1.2390x over previous
#include <cuda_runtime.h>
#include <cuda_bf16.h>
#include <cstdint>
#include <math.h>

#define BDIM 8
#define NDIM 1024
#define DMODEL 512
#define HH 8
#define DKH 64
#define ST 128
#define MROWS (BDIM * NDIM)
#define WSZ (DMODEL * DMODEL)

// ---------------- scratch (device globals) ----------------
__device__ float g_q[MROWS * DMODEL];
__device__ float g_k[MROWS * DMODEL];
__device__ float g_v[MROWS * DMODEL];
__device__ float g_y[MROWS * DMODEL];
__device__ __nv_bfloat16 g_ahi[MROWS * DMODEL];
__device__ __nv_bfloat16 g_alo[MROWS * DMODEL];
__device__ __nv_bfloat16 g_chi[MROWS * DMODEL];
__device__ __nv_bfloat16 g_clo[MROWS * DMODEL];
__device__ __nv_bfloat16 g_whi[4 * WSZ];
__device__ __nv_bfloat16 g_wlo[4 * WSZ];

__device__ __forceinline__ uint32_t smem_to_u32(const void* smem_ptr) {
    uint32_t addr;
    asm("{ .reg .u64 tmp; cvta.to.shared.u64 tmp, %1; cvt.u32.u64 %0, tmp; }"
        : "=r"(addr) : "l"(smem_ptr));
    return addr;
}

#define LDSM_X4(r0, r1, r2, r3, addr)                                          \
    asm volatile("ldmatrix.sync.aligned.m8n8.x4.shared.b16 {%0,%1,%2,%3}, [%4];" \
                 : "=r"(r0), "=r"(r1), "=r"(r2), "=r"(r3) : "r"(addr))

// ---------------------------------------------------------------------------
// split fp32 -> bf16 hi + bf16 lo (residual)
// ---------------------------------------------------------------------------
__global__ __launch_bounds__(256) void split_kernel(
    const float* __restrict__ x, __nv_bfloat16* __restrict__ hi,
    __nv_bfloat16* __restrict__ lo, int n4)
{
    int i = blockIdx.x * 256 + threadIdx.x;
    if (i >= n4) return;
    float4 v = ((const float4*)x)[i];
    union { __nv_bfloat16 b[4]; uint2 u; } H, L;
    H.b[0] = __float2bfloat16(v.x);
    H.b[1] = __float2bfloat16(v.y);
    H.b[2] = __float2bfloat16(v.z);
    H.b[3] = __float2bfloat16(v.w);
    L.b[0] = __float2bfloat16(v.x - __bfloat162float(H.b[0]));
    L.b[1] = __float2bfloat16(v.y - __bfloat162float(H.b[1]));
    L.b[2] = __float2bfloat16(v.z - __bfloat162float(H.b[2]));
    L.b[3] = __float2bfloat16(v.w - __bfloat162float(H.b[3]));
    ((uint2*)hi)[i] = H.u;
    ((uint2*)lo)[i] = L.u;
}

// fused 4-weight split: blockIdx.y selects which weight matrix
__global__ __launch_bounds__(256) void split4_kernel(
    const float* __restrict__ w0, const float* __restrict__ w1,
    const float* __restrict__ w2, const float* __restrict__ w3,
    __nv_bfloat16* __restrict__ hi, __nv_bfloat16* __restrict__ lo)
{
    const int z = blockIdx.y;
    const float* src = (z == 0) ? w0 : (z == 1) ? w1 : (z == 2) ? w2 : w3;
    int i = blockIdx.x * 256 + threadIdx.x;
    float4 v = ((const float4*)src)[i];
    union { __nv_bfloat16 b[4]; uint2 u; } H, L;
    H.b[0] = __float2bfloat16(v.x);
    H.b[1] = __float2bfloat16(v.y);
    H.b[2] = __float2bfloat16(v.z);
    H.b[3] = __float2bfloat16(v.w);
    L.b[0] = __float2bfloat16(v.x - __bfloat162float(H.b[0]));
    L.b[1] = __float2bfloat16(v.y - __bfloat162float(H.b[1]));
    L.b[2] = __float2bfloat16(v.z - __bfloat162float(H.b[2]));
    L.b[3] = __float2bfloat16(v.w - __bfloat162float(H.b[3]));
    ((uint2*)(hi + (size_t)z * WSZ))[i] = H.u;
    ((uint2*)(lo + (size_t)z * WSZ))[i] = L.u;
}

// ---------------------------------------------------------------------------
// HMMA split-bf16 GEMM, 8 warps (each 64x32), ldmatrix + 4-stage cp.async.
// ---------------------------------------------------------------------------
#define SASTR 40
#define HALF_STAGE 10240
#define STAGE_BYTES 20480
#define GEMM_SMEM (4 * STAGE_BYTES)

__global__ __launch_bounds__(256) void gemm_tc(
    const __nv_bfloat16* __restrict__ Ahi, const __nv_bfloat16* __restrict__ Alo,
    const __nv_bfloat16* __restrict__ BhiBase, const __nv_bfloat16* __restrict__ BloBase,
    const float* __restrict__ bias, const float* __restrict__ resid,
    float* __restrict__ C0, float* __restrict__ C1, float* __restrict__ C2)
{
    extern __shared__ char smem[];
    const uint32_t smem_base = smem_to_u32(smem);
    const int tid = threadIdx.x;
    const int lane = tid & 31, warp = tid >> 5;
    const int z = blockIdx.z;
    const __nv_bfloat16* Bhi = BhiBase + (size_t)z * WSZ;
    const __nv_bfloat16* Blo = BloBase + (size_t)z * WSZ;
    float* C = (z == 0) ? C0 : (z == 1) ? C1 : C2;
    const int n0 = blockIdx.x * 128, m0 = blockIdx.y * 128;
    const int wm0 = (warp >> 2) * 64, wn0 = (warp & 3) * 32;

    const int a_row = wm0 + (lane & 15);
    const int a_coff = (lane >> 4) * 8;
    const int b_row = wn0 + (lane & 7) + ((lane >> 4) << 3);
    const int b_coff = ((lane >> 3) & 1) * 8;

    float acc[4][4][4];
#pragma unroll
    for (int mt = 0; mt < 4; mt++)
#pragma unroll
        for (int nt = 0; nt < 4; nt++)
#pragma unroll
            for (int c = 0; c < 4; c++) acc[mt][nt][c] = 0.f;

#define ISSUE_LOAD(sidx, Ap, Bp, kk0) do {                                     \
    int _row = tid >> 1, _hf = tid & 1;                                        \
    uint32_t _sa = smem_base + (sidx) * STAGE_BYTES + _row * 80 + _hf * 32;    \
    uint32_t _sb = _sa + HALF_STAGE;                                           \
    const __nv_bfloat16* _ga = (Ap) + (size_t)(m0 + _row) * DMODEL + (kk0) + _hf * 16; \
    const __nv_bfloat16* _gb = (Bp) + (size_t)(n0 + _row) * DMODEL + (kk0) + _hf * 16; \
    asm volatile("cp.async.cg.shared.global [%0], [%1], 16;"                   \
                 :: "r"(_sa), "l"(_ga) : "memory");                            \
    asm volatile("cp.async.cg.shared.global [%0], [%1], 16;"                   \
                 :: "r"(_sa + 16), "l"(_ga + 8) : "memory");                   \
    asm volatile("cp.async.cg.shared.global [%0], [%1], 16;"                   \
                 :: "r"(_sb), "l"(_gb) : "memory");                            \
    asm volatile("cp.async.cg.shared.global [%0], [%1], 16;"                   \
                 :: "r"(_sb + 16), "l"(_gb + 8) : "memory");                   \
} while (0)

#define CHUNK_SRC(idx, Ap, Bp, K0) \
    const int _p = (idx) >> 4; const int K0 = ((idx) & 15) * 32;               \
    const __nv_bfloat16* Ap = (_p == 2) ? Alo : Ahi;                           \
    const __nv_bfloat16* Bp = (_p == 1) ? Blo : Bhi;

#pragma unroll
    for (int s = 0; s < 3; s++) {
        CHUNK_SRC(s, Ap, Bp, k0);
        ISSUE_LOAD(s, Ap, Bp, k0);
        asm volatile("cp.async.commit_group;" ::: "memory");
    }

    for (int i = 0; i < 48; i++) {
        asm volatile("cp.async.wait_group 2;" ::: "memory");
        __syncthreads();

        const uint32_t As_b = smem_base + (i & 3) * STAGE_BYTES;
        const uint32_t Bs_b = As_b + HALF_STAGE;

#pragma unroll
        for (int ks = 0; ks < 2; ks++) {
            uint32_t af[4][4];
            uint32_t bfr[4][2];
#pragma unroll
            for (int mt = 0; mt < 4; mt++) {
                uint32_t ad = As_b + (uint32_t)(((a_row + mt * 16) * SASTR) + ks * 16 + a_coff) * 2;
                LDSM_X4(af[mt][0], af[mt][1], af[mt][2], af[mt][3], ad);
            }
#pragma unroll
            for (int np = 0; np < 2; np++) {
                uint32_t bd = Bs_b + (uint32_t)(((b_row + np * 16) * SASTR) + ks * 16 + b_coff) * 2;
                LDSM_X4(bfr[np * 2][0], bfr[np * 2][1], bfr[np * 2 + 1][0], bfr[np * 2 + 1][1], bd);
            }
#pragma unroll
            for (int mt = 0; mt < 4; mt++)
#pragma unroll
                for (int nt = 0; nt < 4; nt++) {
                    asm volatile(
                        "mma.sync.aligned.m16n8k16.row.col.f32.bf16.bf16.f32 "
                        "{%0,%1,%2,%3}, {%4,%5,%6,%7}, {%8,%9}, {%0,%1,%2,%3};"
                        : "+f"(acc[mt][nt][0]), "+f"(acc[mt][nt][1]),
                          "+f"(acc[mt][nt][2]), "+f"(acc[mt][nt][3])
                        : "r"(af[mt][0]), "r"(af[mt][1]), "r"(af[mt][2]), "r"(af[mt][3]),
                          "r"(bfr[nt][0]), "r"(bfr[nt][1]));
                }
        }

        const int nxt = i + 3;
        if (nxt < 48) {
            CHUNK_SRC(nxt, Ap, Bp, k0);
            ISSUE_LOAD((nxt & 3), Ap, Bp, k0);
        }
        asm volatile("cp.async.commit_group;" ::: "memory");
    }

#pragma unroll
    for (int mt = 0; mt < 4; mt++) {
        const int r = m0 + wm0 + mt * 16 + (lane >> 2);
#pragma unroll
        for (int nt = 0; nt < 4; nt++) {
            const int cn = n0 + wn0 + nt * 8 + (lane & 3) * 2;
            float2 v0 = make_float2(acc[mt][nt][0], acc[mt][nt][1]);
            float2 v1 = make_float2(acc[mt][nt][2], acc[mt][nt][3]);
            if (bias) {
                float2 b2 = *(const float2*)(bias + cn);
                v0.x += b2.x; v0.y += b2.y;
                v1.x += b2.x; v1.y += b2.y;
            }
            if (resid) {
                float2 r0 = *(const float2*)(resid + (size_t)r * DMODEL + cn);
                float2 r1 = *(const float2*)(resid + (size_t)(r + 8) * DMODEL + cn);
                v0.x += r0.x; v0.y += r0.y;
                v1.x += r1.x; v1.y += r1.y;
            }
            *(float2*)(C + (size_t)r * DMODEL + cn) = v0;
            *(float2*)(C + (size_t)(r + 8) * DMODEL + cn) = v1;
        }
    }
}

// ---------------------------------------------------------------------------
// Star attention v4: round-9 structure (Vs in smem, S aliases Qs/Ks,
// self-dot precomputed, 104KB smem -> 2 CTAs/SM) + fused bf16 hi/lo epilogue.
// ---------------------------------------------------------------------------
#define QS_STR 132
#define S_STR  132
#define V_STR  68
#define OFF_KS (DKH * QS_STR)            // 8448
#define OFF_VS (2 * DKH * QS_STR)        // 16896 (S aliases [0..16896))
#define OFF_SD (OFF_VS + ST * V_STR)     // 25600
#define OFF_ZR (OFF_SD + 128)
#define OFF_PS (OFF_ZR + 128)
#define ATTN_SMEM ((OFF_PS + 128) * 4)   // 103936 bytes

__global__ __launch_bounds__(256, 2) void attn_kernel(
    const float* __restrict__ q, const float* __restrict__ k,
    const float* __restrict__ v, const float* __restrict__ rpe,
    __nv_bfloat16* __restrict__ chi, __nv_bfloat16* __restrict__ clo)
{
    extern __shared__ float sm[];
    float* Qs = sm;
    float* Ks = sm + OFF_KS;
    float* S  = sm;                 // aliases Qs/Ks after phase 1
    float* Vs = sm + OFF_VS;
    float* sd = sm + OFF_SD;
    float* Zr = sm + OFF_ZR;
    float* Ps = sm + OFF_PS;

    const int tid = threadIdx.x;
    const int tx = tid & 15, ty = tid >> 4;
    const int qc = blockIdx.x, h = blockIdx.y, b = blockIdx.z;
    const int i0 = qc * 128;
    const bool has_self = (qc > 0);
    const int lane = tid & 31, wid = tid >> 5;

    const float* rpe_bh = rpe + ((size_t)(b * HH + h)) * NDIM * NDIM;

    // ---- self-dot precompute (pairs of threads per query) ----
    if (has_self) {
        const int i = tid >> 1;
        const int dh = (tid & 1) * 32;
        const float* qrow = q + ((size_t)(b * NDIM + i0 + i)) * DMODEL + h * DKH + dh;
        const float* krow = k + ((size_t)(b * NDIM + i0 + i)) * DMODEL + h * DKH + dh;
        float p = 0.f;
#pragma unroll
        for (int d = 0; d < 32; d += 4) {
            float4 q4 = *(const float4*)(qrow + d);
            float4 k4 = *(const float4*)(krow + d);
            p = fmaf(q4.x, k4.x, p);
            p = fmaf(q4.y, k4.y, p);
            p = fmaf(q4.z, k4.z, p);
            p = fmaf(q4.w, k4.w, p);
        }
        p += __shfl_xor_sync(0xffffffffu, p, 1);
        if (!(tid & 1))
            sd[i] = (p + rpe_bh[(size_t)(i0 + i) * NDIM + (i0 + i)]) * 0.125f;
    }

    // ---- load Q (transposed), K stations (transposed), V stations ----
#pragma unroll
    for (int l = 0; l < 8; l++) {
        int idx = tid + l * 256;
        int row = idx >> 4, c = idx & 15;
        float4 va = *(const float4*)(q + ((size_t)(b * NDIM + i0 + row)) * DMODEL + h * DKH + c * 4);
        Qs[(c * 4 + 0) * QS_STR + row] = va.x;
        Qs[(c * 4 + 1) * QS_STR + row] = va.y;
        Qs[(c * 4 + 2) * QS_STR + row] = va.z;
        Qs[(c * 4 + 3) * QS_STR + row] = va.w;
        float4 vk = *(const float4*)(k + ((size_t)(b * NDIM + row)) * DMODEL + h * DKH + c * 4);
        Ks[(c * 4 + 0) * QS_STR + row] = vk.x;
        Ks[(c * 4 + 1) * QS_STR + row] = vk.y;
        Ks[(c * 4 + 2) * QS_STR + row] = vk.z;
        Ks[(c * 4 + 3) * QS_STR + row] = vk.w;
        float4 vv = *(const float4*)(v + ((size_t)(b * NDIM + row)) * DMODEL + h * DKH + c * 4);
        *(float4*)(Vs + row * V_STR + c * 4) = vv;
    }
    __syncthreads();

    // ---- Phase 1: S = Q.K^T in registers, write into aliased S ----
    {
        float acc[8][8];
#pragma unroll
        for (int i = 0; i < 8; i++)
#pragma unroll
            for (int j = 0; j < 8; j++) acc[i][j] = 0.f;

#pragma unroll 8
        for (int kk = 0; kk < DKH; kk++) {
            float a[8], bb[8];
            *(float4*)&a[0]  = *(float4*)&Qs[kk * QS_STR + ty * 4];
            *(float4*)&a[4]  = *(float4*)&Qs[kk * QS_STR + 64 + ty * 4];
            *(float4*)&bb[0] = *(float4*)&Ks[kk * QS_STR + tx * 4];
            *(float4*)&bb[4] = *(float4*)&Ks[kk * QS_STR + 64 + tx * 4];
#pragma unroll
            for (int i = 0; i < 8; i++)
#pragma unroll
                for (int j = 0; j < 8; j++)
                    acc[i][j] = fmaf(a[i], bb[j], acc[i][j]);
        }
        __syncthreads();   // Qs/Ks reads complete before S overwrite
#pragma unroll
        for (int i = 0; i < 8; i++) {
            int m = (i < 4) ? (ty * 4 + i) : (64 + ty * 4 + i - 4);
#pragma unroll
            for (int jh = 0; jh < 2; jh++) {
                int n = jh * 64 + tx * 4;
                float4 r4 = *(const float4*)(rpe_bh + (size_t)(i0 + m) * NDIM + n);
                float4 c;
                c.x = (acc[i][jh * 4 + 0] + r4.x) * 0.125f;
                c.y = (acc[i][jh * 4 + 1] + r4.y) * 0.125f;
                c.z = (acc[i][jh * 4 + 2] + r4.z) * 0.125f;
                c.w = (acc[i][jh * 4 + 3] + r4.w) * 0.125f;
                *(float4*)(S + m * S_STR + n) = c;
            }
        }
    }
    __syncthreads();

    // ---- Phase 2: row softmax ----
    for (int r16 = 0; r16 < 16; r16++) {
        int i = wid * 16 + r16;
        float4 x = *(float4*)(S + i * S_STR + lane * 4);
        float mx = fmaxf(fmaxf(x.x, x.y), fmaxf(x.z, x.w));
#pragma unroll
        for (int off = 16; off > 0; off >>= 1)
            mx = fmaxf(mx, __shfl_xor_sync(0xffffffffu, mx, off));

        float s_self = -3.0e38f;
        if (has_self) {
            s_self = sd[i];
            mx = fmaxf(mx, s_self);
        }

        float4 e;
        e.x = __expf(x.x - mx);
        e.y = __expf(x.y - mx);
        e.z = __expf(x.z - mx);
        e.w = __expf(x.w - mx);
        *(float4*)(S + i * S_STR + lane * 4) = e;
        float sum = e.x + e.y + e.z + e.w;
#pragma unroll
        for (int off = 16; off > 0; off >>= 1)
            sum += __shfl_xor_sync(0xffffffffu, sum, off);

        float pself = has_self ? __expf(s_self - mx) : 0.f;
        if (lane == 0) {
            Zr[i] = sum + pself;
            Ps[i] = pself;
        }
    }
    __syncthreads();

    // ---- Phase 3: ctx = P.V from smem, fused bf16 hi/lo split store ----
    {
        float acc[8][4];
#pragma unroll
        for (int i = 0; i < 8; i++)
#pragma unroll
            for (int j = 0; j < 4; j++) acc[i][j] = 0.f;

        const int ibase = ty * 8;
#pragma unroll 4
        for (int j = 0; j < ST; j++) {
            float4 v4 = *(float4*)(Vs + j * V_STR + tx * 4);
#pragma unroll
            for (int r = 0; r < 8; r++) {
                float p = S[(ibase + r) * S_STR + j];
                acc[r][0] = fmaf(p, v4.x, acc[r][0]);
                acc[r][1] = fmaf(p, v4.y, acc[r][1]);
                acc[r][2] = fmaf(p, v4.z, acc[r][2]);
                acc[r][3] = fmaf(p, v4.w, acc[r][3]);
            }
        }

#pragma unroll
        for (int r = 0; r < 8; r++) {
            int i = ibase + r;
            float invZ = 1.f / Zr[i];
            float4 o;
            o.x = acc[r][0]; o.y = acc[r][1]; o.z = acc[r][2]; o.w = acc[r][3];
            if (has_self) {
                float ps = Ps[i];
                float4 vs = *(const float4*)(v + ((size_t)(b * NDIM + i0 + i)) * DMODEL + h * DKH + tx * 4);
                o.x = fmaf(ps, vs.x, o.x);
                o.y = fmaf(ps, vs.y, o.y);
                o.z = fmaf(ps, vs.z, o.z);
                o.w = fmaf(ps, vs.w, o.w);
            }
            o.x *= invZ; o.y *= invZ; o.z *= invZ; o.w *= invZ;
            // direct bf16 hi/lo split store
            union { __nv_bfloat16 bb[4]; uint2 u; } H, L;
            H.bb[0] = __float2bfloat16(o.x);
            H.bb[1] = __float2bfloat16(o.y);
            H.bb[2] = __float2bfloat16(o.z);
            H.bb[3] = __float2bfloat16(o.w);
            L.bb[0] = __float2bfloat16(o.x - __bfloat162float(H.bb[0]));
            L.bb[1] = __float2bfloat16(o.y - __bfloat162float(H.bb[1]));
            L.bb[2] = __float2bfloat16(o.z - __bfloat162float(H.bb[2]));
            L.bb[3] = __float2bfloat16(o.w - __bfloat162float(H.bb[3]));
            size_t off = ((size_t)(b * NDIM + i0 + i)) * DMODEL + h * DKH + tx * 4;
            *(uint2*)(chi + off) = H.u;
            *(uint2*)(clo + off) = L.u;
        }
    }
}

// ---------------------------------------------------------------------------
// LayerNorm over rows of 512.
// ---------------------------------------------------------------------------
__global__ __launch_bounds__(128) void ln_kernel(
    const float* __restrict__ y, const float* __restrict__ g,
    const float* __restrict__ bta, float* __restrict__ out)
{
    __shared__ float sh1[4], sh2[4];
    const int row = blockIdx.x, t = threadIdx.x;
    const int lane = t & 31, wid = t >> 5;

    float4 vv = *(const float4*)(y + (size_t)row * DMODEL + t * 4);
    float s  = vv.x + vv.y + vv.z + vv.w;
    float s2 = vv.x * vv.x + vv.y * vv.y + vv.z * vv.z + vv.w * vv.w;
#pragma unroll
    for (int off = 16; off > 0; off >>= 1) {
        s  += __shfl_xor_sync(0xffffffffu, s, off);
        s2 += __shfl_xor_sync(0xffffffffu, s2, off);
    }
    if (lane == 0) { sh1[wid] = s; sh2[wid] = s2; }
    __syncthreads();
    float tot  = sh1[0] + sh1[1] + sh1[2] + sh1[3];
    float tot2 = sh2[0] + sh2[1] + sh2[2] + sh2[3];
    float mu  = tot * (1.f / 512.f);
    float var = tot2 * (1.f / 512.f) - mu * mu;
    float rs  = rsqrtf(var + 1e-6f);

    float4 gg = *(const float4*)(g + t * 4);
    float4 bb = *(const float4*)(bta + t * 4);
    float4 o;
    o.x = (vv.x - mu) * rs * gg.x + bb.x;
    o.y = (vv.y - mu) * rs * gg.y + bb.y;
    o.z = (vv.z - mu) * rs * gg.z + bb.z;
    o.w = (vv.w - mu) * rs * gg.w + bb.w;
    *(float4*)(out + (size_t)row * DMODEL + t * 4) = o;
}

// ---------------------------------------------------------------------------
extern "C" void kernel_launch(void* const* d_in, const int* in_sizes, int n_in,
                              void* d_out, int out_size)
{
    const float* hidden = (const float*)d_in[0];
    const float* rpe    = (const float*)d_in[1];
    const float* Wq     = (const float*)d_in[2];
    const float* Wk     = (const float*)d_in[3];
    const float* Wv     = (const float*)d_in[4];
    const float* fcw    = (const float*)d_in[5];
    const float* fcb    = (const float*)d_in[6];
    const float* lng    = (const float*)d_in[7];
    const float* lnb    = (const float*)d_in[8];
    float* out = (float*)d_out;

    float *qb, *kb, *vb, *yb;
    __nv_bfloat16 *ahi, *alo, *chi, *clo, *whi, *wlo;
    cudaGetSymbolAddress((void**)&qb, g_q);
    cudaGetSymbolAddress((void**)&kb, g_k);
    cudaGetSymbolAddress((void**)&vb, g_v);
    cudaGetSymbolAddress((void**)&yb, g_y);
    cudaGetSymbolAddress((void**)&ahi, g_ahi);
    cudaGetSymbolAddress((void**)&alo, g_alo);
    cudaGetSymbolAddress((void**)&chi, g_chi);
    cudaGetSymbolAddress((void**)&clo, g_clo);
    cudaGetSymbolAddress((void**)&whi, g_whi);
    cudaGetSymbolAddress((void**)&wlo, g_wlo);

    static int attr_set = 0;
    if (!attr_set) {
        cudaFuncSetAttribute(gemm_tc, cudaFuncAttributeMaxDynamicSharedMemorySize, GEMM_SMEM);
        cudaFuncSetAttribute(attn_kernel, cudaFuncAttributeMaxDynamicSharedMemorySize, ATTN_SMEM);
        attr_set = 1;
    }

    const int n4h = MROWS * DMODEL / 4;
    const int n4w = WSZ / 4;

    split_kernel<<<n4h / 256, 256>>>(hidden, ahi, alo, n4h);
    split4_kernel<<<dim3(n4w / 256, 4), 256>>>(Wq, Wk, Wv, fcw, whi, wlo);

    // fused QKV
    gemm_tc<<<dim3(DMODEL / 128, MROWS / 128, 3), 256, GEMM_SMEM>>>(
        ahi, alo, whi, wlo, nullptr, nullptr, qb, kb, vb);

    attn_kernel<<<dim3(NDIM / 128, HH, BDIM), 256, ATTN_SMEM>>>(qb, kb, vb, rpe, chi, clo);

    gemm_tc<<<dim3(DMODEL / 128, MROWS / 128, 1), 256, GEMM_SMEM>>>(
        chi, clo, whi + 3 * WSZ, wlo + 3 * WSZ, fcb, hidden, yb, yb, yb);

    ln_kernel<<<MROWS, 128>>>(yb, lng, lnb, out);
}

// round 13
// speedup vs baseline: 1.5691x; 1.2664x over previous
#include <cuda_runtime.h>
#include <cuda_fp16.h>
#include <cstdint>
#include <math.h>

#define BDIM 8
#define NDIM 1024
#define DMODEL 512
#define HH 8
#define DKH 64
#define ST 128
#define MROWS (BDIM * NDIM)
#define WSZ (DMODEL * DMODEL)

// ---------------- scratch (device globals) ----------------
__device__ float g_q[MROWS * DMODEL];
__device__ float g_k[MROWS * DMODEL];
__device__ float g_v[MROWS * DMODEL];
__device__ float g_y[MROWS * DMODEL];
__device__ __half g_ahi[MROWS * DMODEL];
__device__ __half g_alo[MROWS * DMODEL];
__device__ __half g_chi[MROWS * DMODEL];
__device__ __half g_clo[MROWS * DMODEL];
__device__ __half g_wh[4 * WSZ];

__device__ __forceinline__ uint32_t smem_to_u32(const void* smem_ptr) {
    uint32_t addr;
    asm("{ .reg .u64 tmp; cvta.to.shared.u64 tmp, %1; cvt.u32.u64 %0, tmp; }"
        : "=r"(addr) : "l"(smem_ptr));
    return addr;
}

#define LDSM_X4(r0, r1, r2, r3, addr)                                          \
    asm volatile("ldmatrix.sync.aligned.m8n8.x4.shared.b16 {%0,%1,%2,%3}, [%4];" \
                 : "=r"(r0), "=r"(r1), "=r"(r2), "=r"(r3) : "r"(addr))

// ---------------------------------------------------------------------------
// split fp32 -> fp16 hi + fp16 lo (residual)
// ---------------------------------------------------------------------------
__global__ __launch_bounds__(256) void split_kernel(
    const float* __restrict__ x, __half* __restrict__ hi,
    __half* __restrict__ lo, int n4)
{
    int i = blockIdx.x * 256 + threadIdx.x;
    if (i >= n4) return;
    float4 v = ((const float4*)x)[i];
    union { __half b[4]; uint2 u; } H, L;
    H.b[0] = __float2half_rn(v.x);
    H.b[1] = __float2half_rn(v.y);
    H.b[2] = __float2half_rn(v.z);
    H.b[3] = __float2half_rn(v.w);
    L.b[0] = __float2half_rn(v.x - __half2float(H.b[0]));
    L.b[1] = __float2half_rn(v.y - __half2float(H.b[1]));
    L.b[2] = __float2half_rn(v.z - __half2float(H.b[2]));
    L.b[3] = __float2half_rn(v.w - __half2float(H.b[3]));
    ((uint2*)hi)[i] = H.u;
    ((uint2*)lo)[i] = L.u;
}

// fused 4-weight fp32 -> fp16 convert (hi only)
__global__ __launch_bounds__(256) void conv4_kernel(
    const float* __restrict__ w0, const float* __restrict__ w1,
    const float* __restrict__ w2, const float* __restrict__ w3,
    __half* __restrict__ hi)
{
    const int z = blockIdx.y;
    const float* src = (z == 0) ? w0 : (z == 1) ? w1 : (z == 2) ? w2 : w3;
    int i = blockIdx.x * 256 + threadIdx.x;
    float4 v = ((const float4*)src)[i];
    union { __half b[4]; uint2 u; } H;
    H.b[0] = __float2half_rn(v.x);
    H.b[1] = __float2half_rn(v.y);
    H.b[2] = __float2half_rn(v.z);
    H.b[3] = __float2half_rn(v.w);
    ((uint2*)(hi + (size_t)z * WSZ))[i] = H.u;
}

// ---------------------------------------------------------------------------
// HMMA fp16 2-pass GEMM, 8 warps (each 64x32), ldmatrix + 4-stage cp.async.
// C[m][n] = sum_k A[m][k]*W[n][k] (+bias)(+resid)
// via (Ahi + Alo) * Bh in fp32 accum (mma.sync.m16n8k16.f16).
// CTA 128x128, 32 chunks of K=32 (2 passes x 16). blockIdx.z: QKV fusion.
// ---------------------------------------------------------------------------
#define SASTR 40
#define HALF_STAGE 10240
#define STAGE_BYTES 20480
#define GEMM_SMEM (4 * STAGE_BYTES)

__global__ __launch_bounds__(256) void gemm_tc(
    const __half* __restrict__ Ahi, const __half* __restrict__ Alo,
    const __half* __restrict__ BhBase,
    const float* __restrict__ bias, const float* __restrict__ resid,
    float* __restrict__ C0, float* __restrict__ C1, float* __restrict__ C2)
{
    extern __shared__ char smem[];
    const uint32_t smem_base = smem_to_u32(smem);
    const int tid = threadIdx.x;
    const int lane = tid & 31, warp = tid >> 5;
    const int z = blockIdx.z;
    const __half* Bh = BhBase + (size_t)z * WSZ;
    float* C = (z == 0) ? C0 : (z == 1) ? C1 : C2;
    const int n0 = blockIdx.x * 128, m0 = blockIdx.y * 128;
    const int wm0 = (warp >> 2) * 64, wn0 = (warp & 3) * 32;

    const int a_row = wm0 + (lane & 15);
    const int a_coff = (lane >> 4) * 8;
    const int b_row = wn0 + (lane & 7) + ((lane >> 4) << 3);
    const int b_coff = ((lane >> 3) & 1) * 8;

    float acc[4][4][4];
#pragma unroll
    for (int mt = 0; mt < 4; mt++)
#pragma unroll
        for (int nt = 0; nt < 4; nt++)
#pragma unroll
            for (int c = 0; c < 4; c++) acc[mt][nt][c] = 0.f;

#define ISSUE_LOAD(sidx, Ap, Bp, kk0) do {                                     \
    int _row = tid >> 1, _hf = tid & 1;                                        \
    uint32_t _sa = smem_base + (sidx) * STAGE_BYTES + _row * 80 + _hf * 32;    \
    uint32_t _sb = _sa + HALF_STAGE;                                           \
    const __half* _ga = (Ap) + (size_t)(m0 + _row) * DMODEL + (kk0) + _hf * 16; \
    const __half* _gb = (Bp) + (size_t)(n0 + _row) * DMODEL + (kk0) + _hf * 16; \
    asm volatile("cp.async.cg.shared.global [%0], [%1], 16;"                   \
                 :: "r"(_sa), "l"(_ga) : "memory");                            \
    asm volatile("cp.async.cg.shared.global [%0], [%1], 16;"                   \
                 :: "r"(_sa + 16), "l"(_ga + 8) : "memory");                   \
    asm volatile("cp.async.cg.shared.global [%0], [%1], 16;"                   \
                 :: "r"(_sb), "l"(_gb) : "memory");                            \
    asm volatile("cp.async.cg.shared.global [%0], [%1], 16;"                   \
                 :: "r"(_sb + 16), "l"(_gb + 8) : "memory");                   \
} while (0)

#define CHUNK_SRC(idx, Ap, K0) \
    const int K0 = ((idx) & 15) * 32;                                          \
    const __half* Ap = ((idx) >> 4) ? Alo : Ahi;

    // prologue: 3 stages in flight
#pragma unroll
    for (int s = 0; s < 3; s++) {
        CHUNK_SRC(s, Ap, k0);
        ISSUE_LOAD(s, Ap, Bh, k0);
        asm volatile("cp.async.commit_group;" ::: "memory");
    }

    for (int i = 0; i < 32; i++) {
        asm volatile("cp.async.wait_group 2;" ::: "memory");
        __syncthreads();

        const uint32_t As_b = smem_base + (i & 3) * STAGE_BYTES;
        const uint32_t Bs_b = As_b + HALF_STAGE;

#pragma unroll
        for (int ks = 0; ks < 2; ks++) {
            uint32_t af[4][4];
            uint32_t bfr[4][2];
#pragma unroll
            for (int mt = 0; mt < 4; mt++) {
                uint32_t ad = As_b + (uint32_t)(((a_row + mt * 16) * SASTR) + ks * 16 + a_coff) * 2;
                LDSM_X4(af[mt][0], af[mt][1], af[mt][2], af[mt][3], ad);
            }
#pragma unroll
            for (int np = 0; np < 2; np++) {
                uint32_t bd = Bs_b + (uint32_t)(((b_row + np * 16) * SASTR) + ks * 16 + b_coff) * 2;
                LDSM_X4(bfr[np * 2][0], bfr[np * 2][1], bfr[np * 2 + 1][0], bfr[np * 2 + 1][1], bd);
            }
#pragma unroll
            for (int mt = 0; mt < 4; mt++)
#pragma unroll
                for (int nt = 0; nt < 4; nt++) {
                    asm volatile(
                        "mma.sync.aligned.m16n8k16.row.col.f32.f16.f16.f32 "
                        "{%0,%1,%2,%3}, {%4,%5,%6,%7}, {%8,%9}, {%0,%1,%2,%3};"
                        : "+f"(acc[mt][nt][0]), "+f"(acc[mt][nt][1]),
                          "+f"(acc[mt][nt][2]), "+f"(acc[mt][nt][3])
                        : "r"(af[mt][0]), "r"(af[mt][1]), "r"(af[mt][2]), "r"(af[mt][3]),
                          "r"(bfr[nt][0]), "r"(bfr[nt][1]));
                }
        }

        const int nxt = i + 3;
        if (nxt < 32) {
            CHUNK_SRC(nxt, Ap, k0);
            ISSUE_LOAD((nxt & 3), Ap, Bh, k0);
        }
        asm volatile("cp.async.commit_group;" ::: "memory");
    }

    // epilogue
#pragma unroll
    for (int mt = 0; mt < 4; mt++) {
        const int r = m0 + wm0 + mt * 16 + (lane >> 2);
#pragma unroll
        for (int nt = 0; nt < 4; nt++) {
            const int cn = n0 + wn0 + nt * 8 + (lane & 3) * 2;
            float2 v0 = make_float2(acc[mt][nt][0], acc[mt][nt][1]);
            float2 v1 = make_float2(acc[mt][nt][2], acc[mt][nt][3]);
            if (bias) {
                float2 b2 = *(const float2*)(bias + cn);
                v0.x += b2.x; v0.y += b2.y;
                v1.x += b2.x; v1.y += b2.y;
            }
            if (resid) {
                float2 r0 = *(const float2*)(resid + (size_t)r * DMODEL + cn);
                float2 r1 = *(const float2*)(resid + (size_t)(r + 8) * DMODEL + cn);
                v0.x += r0.x; v0.y += r0.y;
                v1.x += r1.x; v1.y += r1.y;
            }
            *(float2*)(C + (size_t)r * DMODEL + cn) = v0;
            *(float2*)(C + (size_t)(r + 8) * DMODEL + cn) = v1;
        }
    }
}

// ---------------------------------------------------------------------------
// Star attention v4 (unchanged structure): Vs in smem, S aliases Qs/Ks,
// self-dot precomputed, 104KB smem -> 2 CTAs/SM, fused fp16 hi/lo epilogue.
// ---------------------------------------------------------------------------
#define QS_STR 132
#define S_STR  132
#define V_STR  68
#define OFF_KS (DKH * QS_STR)
#define OFF_VS (2 * DKH * QS_STR)
#define OFF_SD (OFF_VS + ST * V_STR)
#define OFF_ZR (OFF_SD + 128)
#define OFF_PS (OFF_ZR + 128)
#define ATTN_SMEM ((OFF_PS + 128) * 4)   // 103936 bytes

__global__ __launch_bounds__(256, 2) void attn_kernel(
    const float* __restrict__ q, const float* __restrict__ k,
    const float* __restrict__ v, const float* __restrict__ rpe,
    __half* __restrict__ chi, __half* __restrict__ clo)
{
    extern __shared__ float sm[];
    float* Qs = sm;
    float* Ks = sm + OFF_KS;
    float* S  = sm;                 // aliases Qs/Ks after phase 1
    float* Vs = sm + OFF_VS;
    float* sd = sm + OFF_SD;
    float* Zr = sm + OFF_ZR;
    float* Ps = sm + OFF_PS;

    const int tid = threadIdx.x;
    const int tx = tid & 15, ty = tid >> 4;
    const int qc = blockIdx.x, h = blockIdx.y, b = blockIdx.z;
    const int i0 = qc * 128;
    const bool has_self = (qc > 0);
    const int lane = tid & 31, wid = tid >> 5;

    const float* rpe_bh = rpe + ((size_t)(b * HH + h)) * NDIM * NDIM;

    // ---- self-dot precompute ----
    if (has_self) {
        const int i = tid >> 1;
        const int dh = (tid & 1) * 32;
        const float* qrow = q + ((size_t)(b * NDIM + i0 + i)) * DMODEL + h * DKH + dh;
        const float* krow = k + ((size_t)(b * NDIM + i0 + i)) * DMODEL + h * DKH + dh;
        float p = 0.f;
#pragma unroll
        for (int d = 0; d < 32; d += 4) {
            float4 q4 = *(const float4*)(qrow + d);
            float4 k4 = *(const float4*)(krow + d);
            p = fmaf(q4.x, k4.x, p);
            p = fmaf(q4.y, k4.y, p);
            p = fmaf(q4.z, k4.z, p);
            p = fmaf(q4.w, k4.w, p);
        }
        p += __shfl_xor_sync(0xffffffffu, p, 1);
        if (!(tid & 1))
            sd[i] = (p + rpe_bh[(size_t)(i0 + i) * NDIM + (i0 + i)]) * 0.125f;
    }

    // ---- load Q (transposed), K stations (transposed), V stations ----
#pragma unroll
    for (int l = 0; l < 8; l++) {
        int idx = tid + l * 256;
        int row = idx >> 4, c = idx & 15;
        float4 va = *(const float4*)(q + ((size_t)(b * NDIM + i0 + row)) * DMODEL + h * DKH + c * 4);
        Qs[(c * 4 + 0) * QS_STR + row] = va.x;
        Qs[(c * 4 + 1) * QS_STR + row] = va.y;
        Qs[(c * 4 + 2) * QS_STR + row] = va.z;
        Qs[(c * 4 + 3) * QS_STR + row] = va.w;
        float4 vk = *(const float4*)(k + ((size_t)(b * NDIM + row)) * DMODEL + h * DKH + c * 4);
        Ks[(c * 4 + 0) * QS_STR + row] = vk.x;
        Ks[(c * 4 + 1) * QS_STR + row] = vk.y;
        Ks[(c * 4 + 2) * QS_STR + row] = vk.z;
        Ks[(c * 4 + 3) * QS_STR + row] = vk.w;
        float4 vv = *(const float4*)(v + ((size_t)(b * NDIM + row)) * DMODEL + h * DKH + c * 4);
        *(float4*)(Vs + row * V_STR + c * 4) = vv;
    }
    __syncthreads();

    // ---- Phase 1: S = Q.K^T ----
    {
        float acc[8][8];
#pragma unroll
        for (int i = 0; i < 8; i++)
#pragma unroll
            for (int j = 0; j < 8; j++) acc[i][j] = 0.f;

#pragma unroll 8
        for (int kk = 0; kk < DKH; kk++) {
            float a[8], bb[8];
            *(float4*)&a[0]  = *(float4*)&Qs[kk * QS_STR + ty * 4];
            *(float4*)&a[4]  = *(float4*)&Qs[kk * QS_STR + 64 + ty * 4];
            *(float4*)&bb[0] = *(float4*)&Ks[kk * QS_STR + tx * 4];
            *(float4*)&bb[4] = *(float4*)&Ks[kk * QS_STR + 64 + tx * 4];
#pragma unroll
            for (int i = 0; i < 8; i++)
#pragma unroll
                for (int j = 0; j < 8; j++)
                    acc[i][j] = fmaf(a[i], bb[j], acc[i][j]);
        }
        __syncthreads();
#pragma unroll
        for (int i = 0; i < 8; i++) {
            int m = (i < 4) ? (ty * 4 + i) : (64 + ty * 4 + i - 4);
#pragma unroll
            for (int jh = 0; jh < 2; jh++) {
                int n = jh * 64 + tx * 4;
                float4 r4 = *(const float4*)(rpe_bh + (size_t)(i0 + m) * NDIM + n);
                float4 c;
                c.x = (acc[i][jh * 4 + 0] + r4.x) * 0.125f;
                c.y = (acc[i][jh * 4 + 1] + r4.y) * 0.125f;
                c.z = (acc[i][jh * 4 + 2] + r4.z) * 0.125f;
                c.w = (acc[i][jh * 4 + 3] + r4.w) * 0.125f;
                *(float4*)(S + m * S_STR + n) = c;
            }
        }
    }
    __syncthreads();

    // ---- Phase 2: row softmax ----
    for (int r16 = 0; r16 < 16; r16++) {
        int i = wid * 16 + r16;
        float4 x = *(float4*)(S + i * S_STR + lane * 4);
        float mx = fmaxf(fmaxf(x.x, x.y), fmaxf(x.z, x.w));
#pragma unroll
        for (int off = 16; off > 0; off >>= 1)
            mx = fmaxf(mx, __shfl_xor_sync(0xffffffffu, mx, off));

        float s_self = -3.0e38f;
        if (has_self) {
            s_self = sd[i];
            mx = fmaxf(mx, s_self);
        }

        float4 e;
        e.x = __expf(x.x - mx);
        e.y = __expf(x.y - mx);
        e.z = __expf(x.z - mx);
        e.w = __expf(x.w - mx);
        *(float4*)(S + i * S_STR + lane * 4) = e;
        float sum = e.x + e.y + e.z + e.w;
#pragma unroll
        for (int off = 16; off > 0; off >>= 1)
            sum += __shfl_xor_sync(0xffffffffu, sum, off);

        float pself = has_self ? __expf(s_self - mx) : 0.f;
        if (lane == 0) {
            Zr[i] = sum + pself;
            Ps[i] = pself;
        }
    }
    __syncthreads();

    // ---- Phase 3: ctx = P.V from smem, fused fp16 hi/lo split store ----
    {
        float acc[8][4];
#pragma unroll
        for (int i = 0; i < 8; i++)
#pragma unroll
            for (int j = 0; j < 4; j++) acc[i][j] = 0.f;

        const int ibase = ty * 8;
#pragma unroll 4
        for (int j = 0; j < ST; j++) {
            float4 v4 = *(float4*)(Vs + j * V_STR + tx * 4);
#pragma unroll
            for (int r = 0; r < 8; r++) {
                float p = S[(ibase + r) * S_STR + j];
                acc[r][0] = fmaf(p, v4.x, acc[r][0]);
                acc[r][1] = fmaf(p, v4.y, acc[r][1]);
                acc[r][2] = fmaf(p, v4.z, acc[r][2]);
                acc[r][3] = fmaf(p, v4.w, acc[r][3]);
            }
        }

#pragma unroll
        for (int r = 0; r < 8; r++) {
            int i = ibase + r;
            float invZ = 1.f / Zr[i];
            float4 o;
            o.x = acc[r][0]; o.y = acc[r][1]; o.z = acc[r][2]; o.w = acc[r][3];
            if (has_self) {
                float ps = Ps[i];
                float4 vs = *(const float4*)(v + ((size_t)(b * NDIM + i0 + i)) * DMODEL + h * DKH + tx * 4);
                o.x = fmaf(ps, vs.x, o.x);
                o.y = fmaf(ps, vs.y, o.y);
                o.z = fmaf(ps, vs.z, o.z);
                o.w = fmaf(ps, vs.w, o.w);
            }
            o.x *= invZ; o.y *= invZ; o.z *= invZ; o.w *= invZ;
            union { __half bb[4]; uint2 u; } H, L;
            H.bb[0] = __float2half_rn(o.x);
            H.bb[1] = __float2half_rn(o.y);
            H.bb[2] = __float2half_rn(o.z);
            H.bb[3] = __float2half_rn(o.w);
            L.bb[0] = __float2half_rn(o.x - __half2float(H.bb[0]));
            L.bb[1] = __float2half_rn(o.y - __half2float(H.bb[1]));
            L.bb[2] = __float2half_rn(o.z - __half2float(H.bb[2]));
            L.bb[3] = __float2half_rn(o.w - __half2float(H.bb[3]));
            size_t off = ((size_t)(b * NDIM + i0 + i)) * DMODEL + h * DKH + tx * 4;
            *(uint2*)(chi + off) = H.u;
            *(uint2*)(clo + off) = L.u;
        }
    }
}

// ---------------------------------------------------------------------------
// LayerNorm over rows of 512.
// ---------------------------------------------------------------------------
__global__ __launch_bounds__(128) void ln_kernel(
    const float* __restrict__ y, const float* __restrict__ g,
    const float* __restrict__ bta, float* __restrict__ out)
{
    __shared__ float sh1[4], sh2[4];
    const int row = blockIdx.x, t = threadIdx.x;
    const int lane = t & 31, wid = t >> 5;

    float4 vv = *(const float4*)(y + (size_t)row * DMODEL + t * 4);
    float s  = vv.x + vv.y + vv.z + vv.w;
    float s2 = vv.x * vv.x + vv.y * vv.y + vv.z * vv.z + vv.w * vv.w;
#pragma unroll
    for (int off = 16; off > 0; off >>= 1) {
        s  += __shfl_xor_sync(0xffffffffu, s, off);
        s2 += __shfl_xor_sync(0xffffffffu, s2, off);
    }
    if (lane == 0) { sh1[wid] = s; sh2[wid] = s2; }
    __syncthreads();
    float tot  = sh1[0] + sh1[1] + sh1[2] + sh1[3];
    float tot2 = sh2[0] + sh2[1] + sh2[2] + sh2[3];
    float mu  = tot * (1.f / 512.f);
    float var = tot2 * (1.f / 512.f) - mu * mu;
    float rs  = rsqrtf(var + 1e-6f);

    float4 gg = *(const float4*)(g + t * 4);
    float4 bb = *(const float4*)(bta + t * 4);
    float4 o;
    o.x = (vv.x - mu) * rs * gg.x + bb.x;
    o.y = (vv.y - mu) * rs * gg.y + bb.y;
    o.z = (vv.z - mu) * rs * gg.z + bb.z;
    o.w = (vv.w - mu) * rs * gg.w + bb.w;
    *(float4*)(out + (size_t)row * DMODEL + t * 4) = o;
}

// ---------------------------------------------------------------------------
extern "C" void kernel_launch(void* const* d_in, const int* in_sizes, int n_in,
                              void* d_out, int out_size)
{
    const float* hidden = (const float*)d_in[0];
    const float* rpe    = (const float*)d_in[1];
    const float* Wq     = (const float*)d_in[2];
    const float* Wk     = (const float*)d_in[3];
    const float* Wv     = (const float*)d_in[4];
    const float* fcw    = (const float*)d_in[5];
    const float* fcb    = (const float*)d_in[6];
    const float* lng    = (const float*)d_in[7];
    const float* lnb    = (const float*)d_in[8];
    float* out = (float*)d_out;

    float *qb, *kb, *vb, *yb;
    __half *ahi, *alo, *chi, *clo, *wh;
    cudaGetSymbolAddress((void**)&qb, g_q);
    cudaGetSymbolAddress((void**)&kb, g_k);
    cudaGetSymbolAddress((void**)&vb, g_v);
    cudaGetSymbolAddress((void**)&yb, g_y);
    cudaGetSymbolAddress((void**)&ahi, g_ahi);
    cudaGetSymbolAddress((void**)&alo, g_alo);
    cudaGetSymbolAddress((void**)&chi, g_chi);
    cudaGetSymbolAddress((void**)&clo, g_clo);
    cudaGetSymbolAddress((void**)&wh, g_wh);

    static int attr_set = 0;
    if (!attr_set) {
        cudaFuncSetAttribute(gemm_tc, cudaFuncAttributeMaxDynamicSharedMemorySize, GEMM_SMEM);
        cudaFuncSetAttribute(attn_kernel, cudaFuncAttributeMaxDynamicSharedMemorySize, ATTN_SMEM);
        attr_set = 1;
    }

    const int n4h = MROWS * DMODEL / 4;
    const int n4w = WSZ / 4;

    split_kernel<<<n4h / 256, 256>>>(hidden, ahi, alo, n4h);
    conv4_kernel<<<dim3(n4w / 256, 4), 256>>>(Wq, Wk, Wv, fcw, wh);

    // fused QKV
    gemm_tc<<<dim3(DMODEL / 128, MROWS / 128, 3), 256, GEMM_SMEM>>>(
        ahi, alo, wh, nullptr, nullptr, qb, kb, vb);

    attn_kernel<<<dim3(NDIM / 128, HH, BDIM), 256, ATTN_SMEM>>>(qb, kb, vb, rpe, chi, clo);

    gemm_tc<<<dim3(DMODEL / 128, MROWS / 128, 1), 256, GEMM_SMEM>>>(
        chi, clo, wh + 3 * WSZ, fcb, hidden, yb, yb, yb);

    ln_kernel<<<MROWS, 128>>>(yb, lng, lnb, out);
}

// round 15
// speedup vs baseline: 1.6635x; 1.0602x over previous
#include <cuda_runtime.h>
#include <cuda_fp16.h>
#include <cstdint>
#include <math.h>

#define BDIM 8
#define NDIM 1024
#define DMODEL 512
#define HH 8
#define DKH 64
#define ST 128
#define MROWS (BDIM * NDIM)
#define WSZ (DMODEL * DMODEL)

// ---------------- scratch (device globals) ----------------
__device__ float g_q[MROWS * DMODEL];
__device__ float g_k[MROWS * DMODEL];
__device__ float g_v[MROWS * DMODEL];
__device__ float g_y[MROWS * DMODEL];
__device__ __half g_ahi[MROWS * DMODEL];
__device__ __half g_alo[MROWS * DMODEL];
__device__ __half g_chi[MROWS * DMODEL];
__device__ __half g_clo[MROWS * DMODEL];
__device__ __half g_wh[4 * WSZ];

__device__ __forceinline__ uint32_t smem_to_u32(const void* smem_ptr) {
    uint32_t addr;
    asm("{ .reg .u64 tmp; cvta.to.shared.u64 tmp, %1; cvt.u32.u64 %0, tmp; }"
        : "=r"(addr) : "l"(smem_ptr));
    return addr;
}

#define LDSM_X4(r0, r1, r2, r3, addr)                                          \
    asm volatile("ldmatrix.sync.aligned.m8n8.x4.shared.b16 {%0,%1,%2,%3}, [%4];" \
                 : "=r"(r0), "=r"(r1), "=r"(r2), "=r"(r3) : "r"(addr))

#define MMA16816(acc, af, bf)                                                  \
    asm volatile(                                                              \
        "mma.sync.aligned.m16n8k16.row.col.f32.f16.f16.f32 "                   \
        "{%0,%1,%2,%3}, {%4,%5,%6,%7}, {%8,%9}, {%0,%1,%2,%3};"                \
        : "+f"((acc)[0]), "+f"((acc)[1]), "+f"((acc)[2]), "+f"((acc)[3])       \
        : "r"((af)[0]), "r"((af)[1]), "r"((af)[2]), "r"((af)[3]),              \
          "r"((bf)[0]), "r"((bf)[1]))

// ---------------------------------------------------------------------------
// split fp32 -> fp16 hi + fp16 lo (residual)
// ---------------------------------------------------------------------------
__global__ __launch_bounds__(256) void split_kernel(
    const float* __restrict__ x, __half* __restrict__ hi,
    __half* __restrict__ lo, int n4)
{
    int i = blockIdx.x * 256 + threadIdx.x;
    if (i >= n4) return;
    float4 v = ((const float4*)x)[i];
    union { __half b[4]; uint2 u; } H, L;
    H.b[0] = __float2half_rn(v.x);
    H.b[1] = __float2half_rn(v.y);
    H.b[2] = __float2half_rn(v.z);
    H.b[3] = __float2half_rn(v.w);
    L.b[0] = __float2half_rn(v.x - __half2float(H.b[0]));
    L.b[1] = __float2half_rn(v.y - __half2float(H.b[1]));
    L.b[2] = __float2half_rn(v.z - __half2float(H.b[2]));
    L.b[3] = __float2half_rn(v.w - __half2float(H.b[3]));
    ((uint2*)hi)[i] = H.u;
    ((uint2*)lo)[i] = L.u;
}

// fused 4-weight fp32 -> fp16 convert (hi only)
__global__ __launch_bounds__(256) void conv4_kernel(
    const float* __restrict__ w0, const float* __restrict__ w1,
    const float* __restrict__ w2, const float* __restrict__ w3,
    __half* __restrict__ hi)
{
    const int z = blockIdx.y;
    const float* src = (z == 0) ? w0 : (z == 1) ? w1 : (z == 2) ? w2 : w3;
    int i = blockIdx.x * 256 + threadIdx.x;
    float4 v = ((const float4*)src)[i];
    union { __half b[4]; uint2 u; } H;
    H.b[0] = __float2half_rn(v.x);
    H.b[1] = __float2half_rn(v.y);
    H.b[2] = __float2half_rn(v.z);
    H.b[3] = __float2half_rn(v.w);
    ((uint2*)(hi + (size_t)z * WSZ))[i] = H.u;
}

// ---------------------------------------------------------------------------
// HMMA fp16 2-pass GEMM, 8 warps (each 64x32), ldmatrix + 4-stage cp.async.
// (unchanged from round 13 — measured at HMMA issue floor)
// ---------------------------------------------------------------------------
#define SASTR 40
#define HALF_STAGE 10240
#define STAGE_BYTES 20480
#define GEMM_SMEM (4 * STAGE_BYTES)

__global__ __launch_bounds__(256) void gemm_tc(
    const __half* __restrict__ Ahi, const __half* __restrict__ Alo,
    const __half* __restrict__ BhBase,
    const float* __restrict__ bias, const float* __restrict__ resid,
    float* __restrict__ C0, float* __restrict__ C1, float* __restrict__ C2)
{
    extern __shared__ char smem[];
    const uint32_t smem_base = smem_to_u32(smem);
    const int tid = threadIdx.x;
    const int lane = tid & 31, warp = tid >> 5;
    const int z = blockIdx.z;
    const __half* Bh = BhBase + (size_t)z * WSZ;
    float* C = (z == 0) ? C0 : (z == 1) ? C1 : C2;
    const int n0 = blockIdx.x * 128, m0 = blockIdx.y * 128;
    const int wm0 = (warp >> 2) * 64, wn0 = (warp & 3) * 32;

    const int a_row = wm0 + (lane & 15);
    const int a_coff = (lane >> 4) * 8;
    const int b_row = wn0 + (lane & 7) + ((lane >> 4) << 3);
    const int b_coff = ((lane >> 3) & 1) * 8;

    float acc[4][4][4];
#pragma unroll
    for (int mt = 0; mt < 4; mt++)
#pragma unroll
        for (int nt = 0; nt < 4; nt++)
#pragma unroll
            for (int c = 0; c < 4; c++) acc[mt][nt][c] = 0.f;

#define ISSUE_LOAD(sidx, Ap, Bp, kk0) do {                                     \
    int _row = tid >> 1, _hf = tid & 1;                                        \
    uint32_t _sa = smem_base + (sidx) * STAGE_BYTES + _row * 80 + _hf * 32;    \
    uint32_t _sb = _sa + HALF_STAGE;                                           \
    const __half* _ga = (Ap) + (size_t)(m0 + _row) * DMODEL + (kk0) + _hf * 16; \
    const __half* _gb = (Bp) + (size_t)(n0 + _row) * DMODEL + (kk0) + _hf * 16; \
    asm volatile("cp.async.cg.shared.global [%0], [%1], 16;"                   \
                 :: "r"(_sa), "l"(_ga) : "memory");                            \
    asm volatile("cp.async.cg.shared.global [%0], [%1], 16;"                   \
                 :: "r"(_sa + 16), "l"(_ga + 8) : "memory");                   \
    asm volatile("cp.async.cg.shared.global [%0], [%1], 16;"                   \
                 :: "r"(_sb), "l"(_gb) : "memory");                            \
    asm volatile("cp.async.cg.shared.global [%0], [%1], 16;"                   \
                 :: "r"(_sb + 16), "l"(_gb + 8) : "memory");                   \
} while (0)

#define CHUNK_SRC(idx, Ap, K0) \
    const int K0 = ((idx) & 15) * 32;                                          \
    const __half* Ap = ((idx) >> 4) ? Alo : Ahi;

#pragma unroll
    for (int s = 0; s < 3; s++) {
        CHUNK_SRC(s, Ap, k0);
        ISSUE_LOAD(s, Ap, Bh, k0);
        asm volatile("cp.async.commit_group;" ::: "memory");
    }

    for (int i = 0; i < 32; i++) {
        asm volatile("cp.async.wait_group 2;" ::: "memory");
        __syncthreads();

        const uint32_t As_b = smem_base + (i & 3) * STAGE_BYTES;
        const uint32_t Bs_b = As_b + HALF_STAGE;

#pragma unroll
        for (int ks = 0; ks < 2; ks++) {
            uint32_t af[4][4];
            uint32_t bfr[4][2];
#pragma unroll
            for (int mt = 0; mt < 4; mt++) {
                uint32_t ad = As_b + (uint32_t)(((a_row + mt * 16) * SASTR) + ks * 16 + a_coff) * 2;
                LDSM_X4(af[mt][0], af[mt][1], af[mt][2], af[mt][3], ad);
            }
#pragma unroll
            for (int np = 0; np < 2; np++) {
                uint32_t bd = Bs_b + (uint32_t)(((b_row + np * 16) * SASTR) + ks * 16 + b_coff) * 2;
                LDSM_X4(bfr[np * 2][0], bfr[np * 2][1], bfr[np * 2 + 1][0], bfr[np * 2 + 1][1], bd);
            }
#pragma unroll
            for (int mt = 0; mt < 4; mt++)
#pragma unroll
                for (int nt = 0; nt < 4; nt++)
                    MMA16816(acc[mt][nt], af[mt], bfr[nt]);
        }

        const int nxt = i + 3;
        if (nxt < 32) {
            CHUNK_SRC(nxt, Ap, k0);
            ISSUE_LOAD((nxt & 3), Ap, Bh, k0);
        }
        asm volatile("cp.async.commit_group;" ::: "memory");
    }

#pragma unroll
    for (int mt = 0; mt < 4; mt++) {
        const int r = m0 + wm0 + mt * 16 + (lane >> 2);
#pragma unroll
        for (int nt = 0; nt < 4; nt++) {
            const int cn = n0 + wn0 + nt * 8 + (lane & 3) * 2;
            float2 v0 = make_float2(acc[mt][nt][0], acc[mt][nt][1]);
            float2 v1 = make_float2(acc[mt][nt][2], acc[mt][nt][3]);
            if (bias) {
                float2 b2 = *(const float2*)(bias + cn);
                v0.x += b2.x; v0.y += b2.y;
                v1.x += b2.x; v1.y += b2.y;
            }
            if (resid) {
                float2 r0 = *(const float2*)(resid + (size_t)r * DMODEL + cn);
                float2 r1 = *(const float2*)(resid + (size_t)(r + 8) * DMODEL + cn);
                v0.x += r0.x; v0.y += r0.y;
                v1.x += r1.x; v1.y += r1.y;
            }
            *(float2*)(C + (size_t)r * DMODEL + cn) = v0;
            *(float2*)(C + (size_t)(r + 8) * DMODEL + cn) = v1;
        }
    }
}

// ---------------------------------------------------------------------------
// Star attention v5: phase 1 (S = Q.K^T) on fp16 HMMA. Q/K live as fp16 in
// smem (stride 72 halfs -> conflict-free ldmatrix); S fp32 aliases them after
// MMA. Phases 2/3 unchanged (SIMT fp32, Vs in smem). 104KB smem, 2 CTAs/SM,
// fused fp16 hi/lo epilogue.
// ---------------------------------------------------------------------------
#define QH_STR 72                        // halfs per row (144B, 16*r mod 128 distinct)
#define S_STR  132
#define V_STR  68
#define KH_BYTE_OFF (128 * QH_STR * 2)   // 18432 bytes (Kh after Qh)
#define OFF_VS (128 * S_STR)             // 16896 floats (S region; Qh+Kh = 9216 floats inside)
#define OFF_SD (OFF_VS + ST * V_STR)     // 25600
#define OFF_ZR (OFF_SD + 128)
#define OFF_PS (OFF_ZR + 128)
#define ATTN_SMEM ((OFF_PS + 128) * 4)   // 103936 bytes

__global__ __launch_bounds__(256, 2) void attn_kernel(
    const float* __restrict__ q, const float* __restrict__ k,
    const float* __restrict__ v, const float* __restrict__ rpe,
    __half* __restrict__ chi, __half* __restrict__ clo)
{
    extern __shared__ float sm[];
    __half* Qh = (__half*)sm;                    // phase1 only
    __half* Kh = (__half*)((char*)sm + KH_BYTE_OFF);
    float* S  = sm;                              // aliases Qh/Kh after phase 1
    float* Vs = sm + OFF_VS;
    float* sd = sm + OFF_SD;
    float* Zr = sm + OFF_ZR;
    float* Ps = sm + OFF_PS;

    const int tid = threadIdx.x;
    const int tx = tid & 15, ty = tid >> 4;
    const int qc = blockIdx.x, h = blockIdx.y, b = blockIdx.z;
    const int i0 = qc * 128;
    const bool has_self = (qc > 0);
    const int lane = tid & 31, wid = tid >> 5;

    const float* rpe_bh = rpe + ((size_t)(b * HH + h)) * NDIM * NDIM;

    // ---- self-dot precompute (pairs of threads per query) ----
    if (has_self) {
        const int i = tid >> 1;
        const int dh = (tid & 1) * 32;
        const float* qrow = q + ((size_t)(b * NDIM + i0 + i)) * DMODEL + h * DKH + dh;
        const float* krow = k + ((size_t)(b * NDIM + i0 + i)) * DMODEL + h * DKH + dh;
        float p = 0.f;
#pragma unroll
        for (int d = 0; d < 32; d += 4) {
            float4 q4 = *(const float4*)(qrow + d);
            float4 k4 = *(const float4*)(krow + d);
            p = fmaf(q4.x, k4.x, p);
            p = fmaf(q4.y, k4.y, p);
            p = fmaf(q4.z, k4.z, p);
            p = fmaf(q4.w, k4.w, p);
        }
        p += __shfl_xor_sync(0xffffffffu, p, 1);
        if (!(tid & 1))
            sd[i] = (p + rpe_bh[(size_t)(i0 + i) * NDIM + (i0 + i)]) * 0.125f;
    }

    // ---- load Q/K (fp16, row-major stride 72) and V (fp32) ----
#pragma unroll
    for (int l = 0; l < 8; l++) {
        int idx = tid + l * 256;
        int row = idx >> 4, c = idx & 15;
        float4 qa = *(const float4*)(q + ((size_t)(b * NDIM + i0 + row)) * DMODEL + h * DKH + c * 4);
        union { __half hh[4]; uint2 u; } Hq;
        Hq.hh[0] = __float2half_rn(qa.x);
        Hq.hh[1] = __float2half_rn(qa.y);
        Hq.hh[2] = __float2half_rn(qa.z);
        Hq.hh[3] = __float2half_rn(qa.w);
        *(uint2*)(Qh + row * QH_STR + c * 4) = Hq.u;
        float4 ka = *(const float4*)(k + ((size_t)(b * NDIM + row)) * DMODEL + h * DKH + c * 4);
        union { __half hh[4]; uint2 u; } Hk;
        Hk.hh[0] = __float2half_rn(ka.x);
        Hk.hh[1] = __float2half_rn(ka.y);
        Hk.hh[2] = __float2half_rn(ka.z);
        Hk.hh[3] = __float2half_rn(ka.w);
        *(uint2*)(Kh + row * QH_STR + c * 4) = Hk.u;
        float4 vv = *(const float4*)(v + ((size_t)(b * NDIM + row)) * DMODEL + h * DKH + c * 4);
        *(float4*)(Vs + row * V_STR + c * 4) = vv;
    }
    __syncthreads();

    // ---- Phase 1: S = Q.K^T via fp16 HMMA (8 warps, 64x32 tiles) ----
    {
        const uint32_t qh_base = smem_to_u32(Qh);
        const uint32_t kh_base = qh_base + KH_BYTE_OFF;
        const int wm0 = (wid >> 2) * 64, wn0 = (wid & 3) * 32;
        const int a_row = wm0 + (lane & 15);
        const int a_coff = (lane >> 4) * 8;
        const int b_row = wn0 + (lane & 7) + ((lane >> 4) << 3);
        const int b_coff = ((lane >> 3) & 1) * 8;

        float acc[4][4][4];
#pragma unroll
        for (int mt = 0; mt < 4; mt++)
#pragma unroll
            for (int nt = 0; nt < 4; nt++)
#pragma unroll
                for (int c = 0; c < 4; c++) acc[mt][nt][c] = 0.f;

#pragma unroll
        for (int ks = 0; ks < 4; ks++) {   // K = 64 = 4 x k16
            uint32_t af[4][4];
            uint32_t bfr[4][2];
#pragma unroll
            for (int mt = 0; mt < 4; mt++) {
                uint32_t ad = qh_base + (uint32_t)(((a_row + mt * 16) * QH_STR) + ks * 16 + a_coff) * 2;
                LDSM_X4(af[mt][0], af[mt][1], af[mt][2], af[mt][3], ad);
            }
#pragma unroll
            for (int np = 0; np < 2; np++) {
                uint32_t bd = kh_base + (uint32_t)(((b_row + np * 16) * QH_STR) + ks * 16 + b_coff) * 2;
                LDSM_X4(bfr[np * 2][0], bfr[np * 2][1], bfr[np * 2 + 1][0], bfr[np * 2 + 1][1], bd);
            }
#pragma unroll
            for (int mt = 0; mt < 4; mt++)
#pragma unroll
                for (int nt = 0; nt < 4; nt++)
                    MMA16816(acc[mt][nt], af[mt], bfr[nt]);
        }
        __syncthreads();   // all ldmatrix reads done before S overwrites Qh/Kh

        // write S with RPE add + scale
#pragma unroll
        for (int mt = 0; mt < 4; mt++) {
            const int r = wm0 + mt * 16 + (lane >> 2);
#pragma unroll
            for (int nt = 0; nt < 4; nt++) {
                const int cn = wn0 + nt * 8 + (lane & 3) * 2;
                float2 p0 = *(const float2*)(rpe_bh + (size_t)(i0 + r) * NDIM + cn);
                float2 p1 = *(const float2*)(rpe_bh + (size_t)(i0 + r + 8) * NDIM + cn);
                S[r * S_STR + cn + 0]       = (acc[mt][nt][0] + p0.x) * 0.125f;
                S[r * S_STR + cn + 1]       = (acc[mt][nt][1] + p0.y) * 0.125f;
                S[(r + 8) * S_STR + cn + 0] = (acc[mt][nt][2] + p1.x) * 0.125f;
                S[(r + 8) * S_STR + cn + 1] = (acc[mt][nt][3] + p1.y) * 0.125f;
            }
        }
    }
    __syncthreads();

    // ---- Phase 2: row softmax ----
    for (int r16 = 0; r16 < 16; r16++) {
        int i = wid * 16 + r16;
        float4 x = *(float4*)(S + i * S_STR + lane * 4);
        float mx = fmaxf(fmaxf(x.x, x.y), fmaxf(x.z, x.w));
#pragma unroll
        for (int off = 16; off > 0; off >>= 1)
            mx = fmaxf(mx, __shfl_xor_sync(0xffffffffu, mx, off));

        float s_self = -3.0e38f;
        if (has_self) {
            s_self = sd[i];
            mx = fmaxf(mx, s_self);
        }

        float4 e;
        e.x = __expf(x.x - mx);
        e.y = __expf(x.y - mx);
        e.z = __expf(x.z - mx);
        e.w = __expf(x.w - mx);
        *(float4*)(S + i * S_STR + lane * 4) = e;
        float sum = e.x + e.y + e.z + e.w;
#pragma unroll
        for (int off = 16; off > 0; off >>= 1)
            sum += __shfl_xor_sync(0xffffffffu, sum, off);

        float pself = has_self ? __expf(s_self - mx) : 0.f;
        if (lane == 0) {
            Zr[i] = sum + pself;
            Ps[i] = pself;
        }
    }
    __syncthreads();

    // ---- Phase 3: ctx = P.V from smem, fused fp16 hi/lo split store ----
    {
        float acc[8][4];
#pragma unroll
        for (int i = 0; i < 8; i++)
#pragma unroll
            for (int j = 0; j < 4; j++) acc[i][j] = 0.f;

        const int ibase = ty * 8;
#pragma unroll 4
        for (int j = 0; j < ST; j++) {
            float4 v4 = *(float4*)(Vs + j * V_STR + tx * 4);
#pragma unroll
            for (int r = 0; r < 8; r++) {
                float p = S[(ibase + r) * S_STR + j];
                acc[r][0] = fmaf(p, v4.x, acc[r][0]);
                acc[r][1] = fmaf(p, v4.y, acc[r][1]);
                acc[r][2] = fmaf(p, v4.z, acc[r][2]);
                acc[r][3] = fmaf(p, v4.w, acc[r][3]);
            }
        }

#pragma unroll
        for (int r = 0; r < 8; r++) {
            int i = ibase + r;
            float invZ = 1.f / Zr[i];
            float4 o;
            o.x = acc[r][0]; o.y = acc[r][1]; o.z = acc[r][2]; o.w = acc[r][3];
            if (has_self) {
                float ps = Ps[i];
                float4 vs = *(const float4*)(v + ((size_t)(b * NDIM + i0 + i)) * DMODEL + h * DKH + tx * 4);
                o.x = fmaf(ps, vs.x, o.x);
                o.y = fmaf(ps, vs.y, o.y);
                o.z = fmaf(ps, vs.z, o.z);
                o.w = fmaf(ps, vs.w, o.w);
            }
            o.x *= invZ; o.y *= invZ; o.z *= invZ; o.w *= invZ;
            union { __half bb[4]; uint2 u; } H, L;
            H.bb[0] = __float2half_rn(o.x);
            H.bb[1] = __float2half_rn(o.y);
            H.bb[2] = __float2half_rn(o.z);
            H.bb[3] = __float2half_rn(o.w);
            L.bb[0] = __float2half_rn(o.x - __half2float(H.bb[0]));
            L.bb[1] = __float2half_rn(o.y - __half2float(H.bb[1]));
            L.bb[2] = __float2half_rn(o.z - __half2float(H.bb[2]));
            L.bb[3] = __float2half_rn(o.w - __half2float(H.bb[3]));
            size_t off = ((size_t)(b * NDIM + i0 + i)) * DMODEL + h * DKH + tx * 4;
            *(uint2*)(chi + off) = H.u;
            *(uint2*)(clo + off) = L.u;
        }
    }
}

// ---------------------------------------------------------------------------
// LayerNorm over rows of 512.
// ---------------------------------------------------------------------------
__global__ __launch_bounds__(128) void ln_kernel(
    const float* __restrict__ y, const float* __restrict__ g,
    const float* __restrict__ bta, float* __restrict__ out)
{
    __shared__ float sh1[4], sh2[4];
    const int row = blockIdx.x, t = threadIdx.x;
    const int lane = t & 31, wid = t >> 5;

    float4 vv = *(const float4*)(y + (size_t)row * DMODEL + t * 4);
    float s  = vv.x + vv.y + vv.z + vv.w;
    float s2 = vv.x * vv.x + vv.y * vv.y + vv.z * vv.z + vv.w * vv.w;
#pragma unroll
    for (int off = 16; off > 0; off >>= 1) {
        s  += __shfl_xor_sync(0xffffffffu, s, off);
        s2 += __shfl_xor_sync(0xffffffffu, s2, off);
    }
    if (lane == 0) { sh1[wid] = s; sh2[wid] = s2; }
    __syncthreads();
    float tot  = sh1[0] + sh1[1] + sh1[2] + sh1[3];
    float tot2 = sh2[0] + sh2[1] + sh2[2] + sh2[3];
    float mu  = tot * (1.f / 512.f);
    float var = tot2 * (1.f / 512.f) - mu * mu;
    float rs  = rsqrtf(var + 1e-6f);

    float4 gg = *(const float4*)(g + t * 4);
    float4 bb = *(const float4*)(bta + t * 4);
    float4 o;
    o.x = (vv.x - mu) * rs * gg.x + bb.x;
    o.y = (vv.y - mu) * rs * gg.y + bb.y;
    o.z = (vv.z - mu) * rs * gg.z + bb.z;
    o.w = (vv.w - mu) * rs * gg.w + bb.w;
    *(float4*)(out + (size_t)row * DMODEL + t * 4) = o;
}

// ---------------------------------------------------------------------------
extern "C" void kernel_launch(void* const* d_in, const int* in_sizes, int n_in,
                              void* d_out, int out_size)
{
    const float* hidden = (const float*)d_in[0];
    const float* rpe    = (const float*)d_in[1];
    const float* Wq     = (const float*)d_in[2];
    const float* Wk     = (const float*)d_in[3];
    const float* Wv     = (const float*)d_in[4];
    const float* fcw    = (const float*)d_in[5];
    const float* fcb    = (const float*)d_in[6];
    const float* lng    = (const float*)d_in[7];
    const float* lnb    = (const float*)d_in[8];
    float* out = (float*)d_out;

    float *qb, *kb, *vb, *yb;
    __half *ahi, *alo, *chi, *clo, *wh;
    cudaGetSymbolAddress((void**)&qb, g_q);
    cudaGetSymbolAddress((void**)&kb, g_k);
    cudaGetSymbolAddress((void**)&vb, g_v);
    cudaGetSymbolAddress((void**)&yb, g_y);
    cudaGetSymbolAddress((void**)&ahi, g_ahi);
    cudaGetSymbolAddress((void**)&alo, g_alo);
    cudaGetSymbolAddress((void**)&chi, g_chi);
    cudaGetSymbolAddress((void**)&clo, g_clo);
    cudaGetSymbolAddress((void**)&wh, g_wh);

    static int attr_set = 0;
    if (!attr_set) {
        cudaFuncSetAttribute(gemm_tc, cudaFuncAttributeMaxDynamicSharedMemorySize, GEMM_SMEM);
        cudaFuncSetAttribute(attn_kernel, cudaFuncAttributeMaxDynamicSharedMemorySize, ATTN_SMEM);
        attr_set = 1;
    }

    const int n4h = MROWS * DMODEL / 4;
    const int n4w = WSZ / 4;

    split_kernel<<<n4h / 256, 256>>>(hidden, ahi, alo, n4h);
    conv4_kernel<<<dim3(n4w / 256, 4), 256>>>(Wq, Wk, Wv, fcw, wh);

    // fused QKV
    gemm_tc<<<dim3(DMODEL / 128, MROWS / 128, 3), 256, GEMM_SMEM>>>(
        ahi, alo, wh, nullptr, nullptr, qb, kb, vb);

    attn_kernel<<<dim3(NDIM / 128, HH, BDIM), 256, ATTN_SMEM>>>(qb, kb, vb, rpe, chi, clo);

    gemm_tc<<<dim3(DMODEL / 128, MROWS / 128, 1), 256, GEMM_SMEM>>>(
        chi, clo, wh + 3 * WSZ, fcb, hidden, yb, yb, yb);

    ln_kernel<<<MROWS, 128>>>(yb, lng, lnb, out);
}

// round 16
// speedup vs baseline: 2.2517x; 1.3536x over previous
#include <cuda_runtime.h>
#include <cuda_fp16.h>
#include <cstdint>
#include <math.h>

#define BDIM 8
#define NDIM 1024
#define DMODEL 512
#define HH 8
#define DKH 64
#define ST 128
#define MROWS (BDIM * NDIM)
#define WSZ (DMODEL * DMODEL)

// ---------------- scratch (device globals) ----------------
__device__ float g_q[MROWS * DMODEL];
__device__ float g_k[MROWS * DMODEL];
__device__ float g_v[MROWS * DMODEL];
__device__ float g_y[MROWS * DMODEL];
__device__ __half g_ah[MROWS * DMODEL];
__device__ __half g_ch[MROWS * DMODEL];
__device__ __half g_wh[4 * WSZ];

__device__ __forceinline__ uint32_t smem_to_u32(const void* smem_ptr) {
    uint32_t addr;
    asm("{ .reg .u64 tmp; cvta.to.shared.u64 tmp, %1; cvt.u32.u64 %0, tmp; }"
        : "=r"(addr) : "l"(smem_ptr));
    return addr;
}

#define LDSM_X4(r0, r1, r2, r3, addr)                                          \
    asm volatile("ldmatrix.sync.aligned.m8n8.x4.shared.b16 {%0,%1,%2,%3}, [%4];" \
                 : "=r"(r0), "=r"(r1), "=r"(r2), "=r"(r3) : "r"(addr))

#define MMA16816(acc, af, bf)                                                  \
    asm volatile(                                                              \
        "mma.sync.aligned.m16n8k16.row.col.f32.f16.f16.f32 "                   \
        "{%0,%1,%2,%3}, {%4,%5,%6,%7}, {%8,%9}, {%0,%1,%2,%3};"                \
        : "+f"((acc)[0]), "+f"((acc)[1]), "+f"((acc)[2]), "+f"((acc)[3])       \
        : "r"((af)[0]), "r"((af)[1]), "r"((af)[2]), "r"((af)[3]),              \
          "r"((bf)[0]), "r"((bf)[1]))

// ---------------------------------------------------------------------------
// convert fp32 -> fp16
// ---------------------------------------------------------------------------
__global__ __launch_bounds__(256) void conv_kernel(
    const float* __restrict__ x, __half* __restrict__ hi, int n4)
{
    int i = blockIdx.x * 256 + threadIdx.x;
    if (i >= n4) return;
    float4 v = ((const float4*)x)[i];
    union { __half b[4]; uint2 u; } H;
    H.b[0] = __float2half_rn(v.x);
    H.b[1] = __float2half_rn(v.y);
    H.b[2] = __float2half_rn(v.z);
    H.b[3] = __float2half_rn(v.w);
    ((uint2*)hi)[i] = H.u;
}

// fused 4-weight fp32 -> fp16 convert
__global__ __launch_bounds__(256) void conv4_kernel(
    const float* __restrict__ w0, const float* __restrict__ w1,
    const float* __restrict__ w2, const float* __restrict__ w3,
    __half* __restrict__ hi)
{
    const int z = blockIdx.y;
    const float* src = (z == 0) ? w0 : (z == 1) ? w1 : (z == 2) ? w2 : w3;
    int i = blockIdx.x * 256 + threadIdx.x;
    float4 v = ((const float4*)src)[i];
    union { __half b[4]; uint2 u; } H;
    H.b[0] = __float2half_rn(v.x);
    H.b[1] = __float2half_rn(v.y);
    H.b[2] = __float2half_rn(v.z);
    H.b[3] = __float2half_rn(v.w);
    ((uint2*)(hi + (size_t)z * WSZ))[i] = H.u;
}

// ---------------------------------------------------------------------------
// HMMA fp16 single-pass GEMM, 8 warps (each 64x32), ldmatrix + 4-stage cp.async.
// C[m][n] = sum_k A[m][k]*W[n][k] (+bias)(+resid), fp32 accum.
// CTA 128x128, 16 chunks of K=32. blockIdx.z: QKV fusion.
// ---------------------------------------------------------------------------
#define SASTR 40
#define HALF_STAGE 10240
#define STAGE_BYTES 20480
#define GEMM_SMEM (4 * STAGE_BYTES)

__global__ __launch_bounds__(256) void gemm_tc(
    const __half* __restrict__ Ah,
    const __half* __restrict__ BhBase,
    const float* __restrict__ bias, const float* __restrict__ resid,
    float* __restrict__ C0, float* __restrict__ C1, float* __restrict__ C2)
{
    extern __shared__ char smem[];
    const uint32_t smem_base = smem_to_u32(smem);
    const int tid = threadIdx.x;
    const int lane = tid & 31, warp = tid >> 5;
    const int z = blockIdx.z;
    const __half* Bh = BhBase + (size_t)z * WSZ;
    float* C = (z == 0) ? C0 : (z == 1) ? C1 : C2;
    const int n0 = blockIdx.x * 128, m0 = blockIdx.y * 128;
    const int wm0 = (warp >> 2) * 64, wn0 = (warp & 3) * 32;

    const int a_row = wm0 + (lane & 15);
    const int a_coff = (lane >> 4) * 8;
    const int b_row = wn0 + (lane & 7) + ((lane >> 4) << 3);
    const int b_coff = ((lane >> 3) & 1) * 8;

    float acc[4][4][4];
#pragma unroll
    for (int mt = 0; mt < 4; mt++)
#pragma unroll
        for (int nt = 0; nt < 4; nt++)
#pragma unroll
            for (int c = 0; c < 4; c++) acc[mt][nt][c] = 0.f;

#define ISSUE_LOAD(sidx, kk0) do {                                             \
    int _row = tid >> 1, _hf = tid & 1;                                        \
    uint32_t _sa = smem_base + (sidx) * STAGE_BYTES + _row * 80 + _hf * 32;    \
    uint32_t _sb = _sa + HALF_STAGE;                                           \
    const __half* _ga = Ah + (size_t)(m0 + _row) * DMODEL + (kk0) + _hf * 16;  \
    const __half* _gb = Bh + (size_t)(n0 + _row) * DMODEL + (kk0) + _hf * 16;  \
    asm volatile("cp.async.cg.shared.global [%0], [%1], 16;"                   \
                 :: "r"(_sa), "l"(_ga) : "memory");                            \
    asm volatile("cp.async.cg.shared.global [%0], [%1], 16;"                   \
                 :: "r"(_sa + 16), "l"(_ga + 8) : "memory");                   \
    asm volatile("cp.async.cg.shared.global [%0], [%1], 16;"                   \
                 :: "r"(_sb), "l"(_gb) : "memory");                            \
    asm volatile("cp.async.cg.shared.global [%0], [%1], 16;"                   \
                 :: "r"(_sb + 16), "l"(_gb + 8) : "memory");                   \
} while (0)

    // prologue: 3 stages in flight
#pragma unroll
    for (int s = 0; s < 3; s++) {
        ISSUE_LOAD(s, s * 32);
        asm volatile("cp.async.commit_group;" ::: "memory");
    }

    for (int i = 0; i < 16; i++) {
        asm volatile("cp.async.wait_group 2;" ::: "memory");
        __syncthreads();

        const uint32_t As_b = smem_base + (i & 3) * STAGE_BYTES;
        const uint32_t Bs_b = As_b + HALF_STAGE;

#pragma unroll
        for (int ks = 0; ks < 2; ks++) {
            uint32_t af[4][4];
            uint32_t bfr[4][2];
#pragma unroll
            for (int mt = 0; mt < 4; mt++) {
                uint32_t ad = As_b + (uint32_t)(((a_row + mt * 16) * SASTR) + ks * 16 + a_coff) * 2;
                LDSM_X4(af[mt][0], af[mt][1], af[mt][2], af[mt][3], ad);
            }
#pragma unroll
            for (int np = 0; np < 2; np++) {
                uint32_t bd = Bs_b + (uint32_t)(((b_row + np * 16) * SASTR) + ks * 16 + b_coff) * 2;
                LDSM_X4(bfr[np * 2][0], bfr[np * 2][1], bfr[np * 2 + 1][0], bfr[np * 2 + 1][1], bd);
            }
#pragma unroll
            for (int mt = 0; mt < 4; mt++)
#pragma unroll
                for (int nt = 0; nt < 4; nt++)
                    MMA16816(acc[mt][nt], af[mt], bfr[nt]);
        }

        const int nxt = i + 3;
        if (nxt < 16) {
            ISSUE_LOAD((nxt & 3), nxt * 32);
        }
        asm volatile("cp.async.commit_group;" ::: "memory");
    }

    // epilogue
#pragma unroll
    for (int mt = 0; mt < 4; mt++) {
        const int r = m0 + wm0 + mt * 16 + (lane >> 2);
#pragma unroll
        for (int nt = 0; nt < 4; nt++) {
            const int cn = n0 + wn0 + nt * 8 + (lane & 3) * 2;
            float2 v0 = make_float2(acc[mt][nt][0], acc[mt][nt][1]);
            float2 v1 = make_float2(acc[mt][nt][2], acc[mt][nt][3]);
            if (bias) {
                float2 b2 = *(const float2*)(bias + cn);
                v0.x += b2.x; v0.y += b2.y;
                v1.x += b2.x; v1.y += b2.y;
            }
            if (resid) {
                float2 r0 = *(const float2*)(resid + (size_t)r * DMODEL + cn);
                float2 r1 = *(const float2*)(resid + (size_t)(r + 8) * DMODEL + cn);
                v0.x += r0.x; v0.y += r0.y;
                v1.x += r1.x; v1.y += r1.y;
            }
            *(float2*)(C + (size_t)r * DMODEL + cn) = v0;
            *(float2*)(C + (size_t)(r + 8) * DMODEL + cn) = v1;
        }
    }
}

// ---------------------------------------------------------------------------
// Star attention v5 (unchanged): phase 1 on fp16 HMMA, phases 2/3 SIMT fp32,
// Vs in smem, 104KB smem / 2 CTAs/SM, epilogue writes fp16 ctx (hi only).
// ---------------------------------------------------------------------------
#define QH_STR 72
#define S_STR  132
#define V_STR  68
#define KH_BYTE_OFF (128 * QH_STR * 2)
#define OFF_VS (128 * S_STR)
#define OFF_SD (OFF_VS + ST * V_STR)
#define OFF_ZR (OFF_SD + 128)
#define OFF_PS (OFF_ZR + 128)
#define ATTN_SMEM ((OFF_PS + 128) * 4)   // 103936 bytes

__global__ __launch_bounds__(256, 2) void attn_kernel(
    const float* __restrict__ q, const float* __restrict__ k,
    const float* __restrict__ v, const float* __restrict__ rpe,
    __half* __restrict__ chi)
{
    extern __shared__ float sm[];
    __half* Qh = (__half*)sm;
    __half* Kh = (__half*)((char*)sm + KH_BYTE_OFF);
    float* S  = sm;
    float* Vs = sm + OFF_VS;
    float* sd = sm + OFF_SD;
    float* Zr = sm + OFF_ZR;
    float* Ps = sm + OFF_PS;

    const int tid = threadIdx.x;
    const int tx = tid & 15, ty = tid >> 4;
    const int qc = blockIdx.x, h = blockIdx.y, b = blockIdx.z;
    const int i0 = qc * 128;
    const bool has_self = (qc > 0);
    const int lane = tid & 31, wid = tid >> 5;

    const float* rpe_bh = rpe + ((size_t)(b * HH + h)) * NDIM * NDIM;

    // ---- self-dot precompute ----
    if (has_self) {
        const int i = tid >> 1;
        const int dh = (tid & 1) * 32;
        const float* qrow = q + ((size_t)(b * NDIM + i0 + i)) * DMODEL + h * DKH + dh;
        const float* krow = k + ((size_t)(b * NDIM + i0 + i)) * DMODEL + h * DKH + dh;
        float p = 0.f;
#pragma unroll
        for (int d = 0; d < 32; d += 4) {
            float4 q4 = *(const float4*)(qrow + d);
            float4 k4 = *(const float4*)(krow + d);
            p = fmaf(q4.x, k4.x, p);
            p = fmaf(q4.y, k4.y, p);
            p = fmaf(q4.z, k4.z, p);
            p = fmaf(q4.w, k4.w, p);
        }
        p += __shfl_xor_sync(0xffffffffu, p, 1);
        if (!(tid & 1))
            sd[i] = (p + rpe_bh[(size_t)(i0 + i) * NDIM + (i0 + i)]) * 0.125f;
    }

    // ---- load Q/K (fp16) and V (fp32) ----
#pragma unroll
    for (int l = 0; l < 8; l++) {
        int idx = tid + l * 256;
        int row = idx >> 4, c = idx & 15;
        float4 qa = *(const float4*)(q + ((size_t)(b * NDIM + i0 + row)) * DMODEL + h * DKH + c * 4);
        union { __half hh[4]; uint2 u; } Hq;
        Hq.hh[0] = __float2half_rn(qa.x);
        Hq.hh[1] = __float2half_rn(qa.y);
        Hq.hh[2] = __float2half_rn(qa.z);
        Hq.hh[3] = __float2half_rn(qa.w);
        *(uint2*)(Qh + row * QH_STR + c * 4) = Hq.u;
        float4 ka = *(const float4*)(k + ((size_t)(b * NDIM + row)) * DMODEL + h * DKH + c * 4);
        union { __half hh[4]; uint2 u; } Hk;
        Hk.hh[0] = __float2half_rn(ka.x);
        Hk.hh[1] = __float2half_rn(ka.y);
        Hk.hh[2] = __float2half_rn(ka.z);
        Hk.hh[3] = __float2half_rn(ka.w);
        *(uint2*)(Kh + row * QH_STR + c * 4) = Hk.u;
        float4 vv = *(const float4*)(v + ((size_t)(b * NDIM + row)) * DMODEL + h * DKH + c * 4);
        *(float4*)(Vs + row * V_STR + c * 4) = vv;
    }
    __syncthreads();

    // ---- Phase 1: S = Q.K^T via fp16 HMMA ----
    {
        const uint32_t qh_base = smem_to_u32(Qh);
        const uint32_t kh_base = qh_base + KH_BYTE_OFF;
        const int wm0 = (wid >> 2) * 64, wn0 = (wid & 3) * 32;
        const int a_row = wm0 + (lane & 15);
        const int a_coff = (lane >> 4) * 8;
        const int b_row = wn0 + (lane & 7) + ((lane >> 4) << 3);
        const int b_coff = ((lane >> 3) & 1) * 8;

        float acc[4][4][4];
#pragma unroll
        for (int mt = 0; mt < 4; mt++)
#pragma unroll
            for (int nt = 0; nt < 4; nt++)
#pragma unroll
                for (int c = 0; c < 4; c++) acc[mt][nt][c] = 0.f;

#pragma unroll
        for (int ks = 0; ks < 4; ks++) {
            uint32_t af[4][4];
            uint32_t bfr[4][2];
#pragma unroll
            for (int mt = 0; mt < 4; mt++) {
                uint32_t ad = qh_base + (uint32_t)(((a_row + mt * 16) * QH_STR) + ks * 16 + a_coff) * 2;
                LDSM_X4(af[mt][0], af[mt][1], af[mt][2], af[mt][3], ad);
            }
#pragma unroll
            for (int np = 0; np < 2; np++) {
                uint32_t bd = kh_base + (uint32_t)(((b_row + np * 16) * QH_STR) + ks * 16 + b_coff) * 2;
                LDSM_X4(bfr[np * 2][0], bfr[np * 2][1], bfr[np * 2 + 1][0], bfr[np * 2 + 1][1], bd);
            }
#pragma unroll
            for (int mt = 0; mt < 4; mt++)
#pragma unroll
                for (int nt = 0; nt < 4; nt++)
                    MMA16816(acc[mt][nt], af[mt], bfr[nt]);
        }
        __syncthreads();

        // write S with RPE add + scale
#pragma unroll
        for (int mt = 0; mt < 4; mt++) {
            const int r = wm0 + mt * 16 + (lane >> 2);
#pragma unroll
            for (int nt = 0; nt < 4; nt++) {
                const int cn = wn0 + nt * 8 + (lane & 3) * 2;
                float2 p0 = *(const float2*)(rpe_bh + (size_t)(i0 + r) * NDIM + cn);
                float2 p1 = *(const float2*)(rpe_bh + (size_t)(i0 + r + 8) * NDIM + cn);
                S[r * S_STR + cn + 0]       = (acc[mt][nt][0] + p0.x) * 0.125f;
                S[r * S_STR + cn + 1]       = (acc[mt][nt][1] + p0.y) * 0.125f;
                S[(r + 8) * S_STR + cn + 0] = (acc[mt][nt][2] + p1.x) * 0.125f;
                S[(r + 8) * S_STR + cn + 1] = (acc[mt][nt][3] + p1.y) * 0.125f;
            }
        }
    }
    __syncthreads();

    // ---- Phase 2: row softmax ----
    for (int r16 = 0; r16 < 16; r16++) {
        int i = wid * 16 + r16;
        float4 x = *(float4*)(S + i * S_STR + lane * 4);
        float mx = fmaxf(fmaxf(x.x, x.y), fmaxf(x.z, x.w));
#pragma unroll
        for (int off = 16; off > 0; off >>= 1)
            mx = fmaxf(mx, __shfl_xor_sync(0xffffffffu, mx, off));

        float s_self = -3.0e38f;
        if (has_self) {
            s_self = sd[i];
            mx = fmaxf(mx, s_self);
        }

        float4 e;
        e.x = __expf(x.x - mx);
        e.y = __expf(x.y - mx);
        e.z = __expf(x.z - mx);
        e.w = __expf(x.w - mx);
        *(float4*)(S + i * S_STR + lane * 4) = e;
        float sum = e.x + e.y + e.z + e.w;
#pragma unroll
        for (int off = 16; off > 0; off >>= 1)
            sum += __shfl_xor_sync(0xffffffffu, sum, off);

        float pself = has_self ? __expf(s_self - mx) : 0.f;
        if (lane == 0) {
            Zr[i] = sum + pself;
            Ps[i] = pself;
        }
    }
    __syncthreads();

    // ---- Phase 3: ctx = P.V from smem, fp16 ctx store ----
    {
        float acc[8][4];
#pragma unroll
        for (int i = 0; i < 8; i++)
#pragma unroll
            for (int j = 0; j < 4; j++) acc[i][j] = 0.f;

        const int ibase = ty * 8;
#pragma unroll 4
        for (int j = 0; j < ST; j++) {
            float4 v4 = *(float4*)(Vs + j * V_STR + tx * 4);
#pragma unroll
            for (int r = 0; r < 8; r++) {
                float p = S[(ibase + r) * S_STR + j];
                acc[r][0] = fmaf(p, v4.x, acc[r][0]);
                acc[r][1] = fmaf(p, v4.y, acc[r][1]);
                acc[r][2] = fmaf(p, v4.z, acc[r][2]);
                acc[r][3] = fmaf(p, v4.w, acc[r][3]);
            }
        }

#pragma unroll
        for (int r = 0; r < 8; r++) {
            int i = ibase + r;
            float invZ = 1.f / Zr[i];
            float4 o;
            o.x = acc[r][0]; o.y = acc[r][1]; o.z = acc[r][2]; o.w = acc[r][3];
            if (has_self) {
                float ps = Ps[i];
                float4 vs = *(const float4*)(v + ((size_t)(b * NDIM + i0 + i)) * DMODEL + h * DKH + tx * 4);
                o.x = fmaf(ps, vs.x, o.x);
                o.y = fmaf(ps, vs.y, o.y);
                o.z = fmaf(ps, vs.z, o.z);
                o.w = fmaf(ps, vs.w, o.w);
            }
            o.x *= invZ; o.y *= invZ; o.z *= invZ; o.w *= invZ;
            union { __half bb[4]; uint2 u; } H;
            H.bb[0] = __float2half_rn(o.x);
            H.bb[1] = __float2half_rn(o.y);
            H.bb[2] = __float2half_rn(o.z);
            H.bb[3] = __float2half_rn(o.w);
            size_t off = ((size_t)(b * NDIM + i0 + i)) * DMODEL + h * DKH + tx * 4;
            *(uint2*)(chi + off) = H.u;
        }
    }
}

// ---------------------------------------------------------------------------
// LayerNorm over rows of 512.
// ---------------------------------------------------------------------------
__global__ __launch_bounds__(128) void ln_kernel(
    const float* __restrict__ y, const float* __restrict__ g,
    const float* __restrict__ bta, float* __restrict__ out)
{
    __shared__ float sh1[4], sh2[4];
    const int row = blockIdx.x, t = threadIdx.x;
    const int lane = t & 31, wid = t >> 5;

    float4 vv = *(const float4*)(y + (size_t)row * DMODEL + t * 4);
    float s  = vv.x + vv.y + vv.z + vv.w;
    float s2 = vv.x * vv.x + vv.y * vv.y + vv.z * vv.z + vv.w * vv.w;
#pragma unroll
    for (int off = 16; off > 0; off >>= 1) {
        s  += __shfl_xor_sync(0xffffffffu, s, off);
        s2 += __shfl_xor_sync(0xffffffffu, s2, off);
    }
    if (lane == 0) { sh1[wid] = s; sh2[wid] = s2; }
    __syncthreads();
    float tot  = sh1[0] + sh1[1] + sh1[2] + sh1[3];
    float tot2 = sh2[0] + sh2[1] + sh2[2] + sh2[3];
    float mu  = tot * (1.f / 512.f);
    float var = tot2 * (1.f / 512.f) - mu * mu;
    float rs  = rsqrtf(var + 1e-6f);

    float4 gg = *(const float4*)(g + t * 4);
    float4 bb = *(const float4*)(bta + t * 4);
    float4 o;
    o.x = (vv.x - mu) * rs * gg.x + bb.x;
    o.y = (vv.y - mu) * rs * gg.y + bb.y;
    o.z = (vv.z - mu) * rs * gg.z + bb.z;
    o.w = (vv.w - mu) * rs * gg.w + bb.w;
    *(float4*)(out + (size_t)row * DMODEL + t * 4) = o;
}

// ---------------------------------------------------------------------------
extern "C" void kernel_launch(void* const* d_in, const int* in_sizes, int n_in,
                              void* d_out, int out_size)
{
    const float* hidden = (const float*)d_in[0];
    const float* rpe    = (const float*)d_in[1];
    const float* Wq     = (const float*)d_in[2];
    const float* Wk     = (const float*)d_in[3];
    const float* Wv     = (const float*)d_in[4];
    const float* fcw    = (const float*)d_in[5];
    const float* fcb    = (const float*)d_in[6];
    const float* lng    = (const float*)d_in[7];
    const float* lnb    = (const float*)d_in[8];
    float* out = (float*)d_out;

    float *qb, *kb, *vb, *yb;
    __half *ah, *ch, *wh;
    cudaGetSymbolAddress((void**)&qb, g_q);
    cudaGetSymbolAddress((void**)&kb, g_k);
    cudaGetSymbolAddress((void**)&vb, g_v);
    cudaGetSymbolAddress((void**)&yb, g_y);
    cudaGetSymbolAddress((void**)&ah, g_ah);
    cudaGetSymbolAddress((void**)&ch, g_ch);
    cudaGetSymbolAddress((void**)&wh, g_wh);

    static int attr_set = 0;
    if (!attr_set) {
        cudaFuncSetAttribute(gemm_tc, cudaFuncAttributeMaxDynamicSharedMemorySize, GEMM_SMEM);
        cudaFuncSetAttribute(attn_kernel, cudaFuncAttributeMaxDynamicSharedMemorySize, ATTN_SMEM);
        attr_set = 1;
    }

    const int n4h = MROWS * DMODEL / 4;
    const int n4w = WSZ / 4;

    conv_kernel<<<n4h / 256, 256>>>(hidden, ah, n4h);
    conv4_kernel<<<dim3(n4w / 256, 4), 256>>>(Wq, Wk, Wv, fcw, wh);

    // fused QKV (single-pass fp16)
    gemm_tc<<<dim3(DMODEL / 128, MROWS / 128, 3), 256, GEMM_SMEM>>>(
        ah, wh, nullptr, nullptr, qb, kb, vb);

    attn_kernel<<<dim3(NDIM / 128, HH, BDIM), 256, ATTN_SMEM>>>(qb, kb, vb, rpe, ch);

    gemm_tc<<<dim3(DMODEL / 128, MROWS / 128, 1), 256, GEMM_SMEM>>>(
        ch, wh + 3 * WSZ, fcb, hidden, yb, yb, yb);

    ln_kernel<<<MROWS, 128>>>(yb, lng, lnb, out);
}